// round 3
// baseline (speedup 1.0000x reference)
#include <cuda_runtime.h>
#include <cuda_bf16.h>
#include <cstdint>

#define EPS 1e-5f

static constexpr int MAX_N = 50048;    // nodes (actual 50000)
static constexpr int MAX_E = 600064;   // edges (actual 600000)

// ---------------- scratch (device globals; no allocation allowed) ------------
__device__ float  g_deg[MAX_N];
__device__ int    g_cnt[MAX_N];
__device__ int    g_fill[MAX_N];
__device__ int    g_rowptr[MAX_N + 1];
__device__ int2   g_csr[MAX_E];        // (src, norm-bits)
__device__ float  g_dinv[MAX_N];
__device__ float  g_normself[MAX_N];
__device__ float4 g_h2[MAX_N * 32];    // GEMM output (up to 128 f/node)
__device__ float4 g_out[MAX_N * 32];   // aggregation output
__device__ float  g_stats[256];        // [0..128) sum, [128..256) sumsq
__device__ __align__(16) float g_scale[128];
__device__ __align__(16) float g_shift[128];

// ---------------- prep kernels ------------------------------------------------
__global__ void k_init(float* deg, int* cnt, int n) {
    int i = blockIdx.x * blockDim.x + threadIdx.x;
    if (i < n) { deg[i] = 1.0f; cnt[i] = 0; }   // self loop weight 1
}

__global__ void k_prep_edge(const int* __restrict__ dst, const float* __restrict__ w,
                            float* deg, int* cnt, int e) {
    int i = blockIdx.x * blockDim.x + threadIdx.x;
    if (i < e) {
        int d = dst[i];
        atomicAdd(deg + d, w[i]);
        atomicAdd(cnt + d, 1);
    }
}

__global__ void k_dinv(const float* __restrict__ deg, float* dinv, float* normself, int n) {
    int i = blockIdx.x * blockDim.x + threadIdx.x;
    if (i < n) {
        float d = deg[i];
        float r = (d > 0.0f) ? rsqrtf(d) : 0.0f;
        dinv[i] = r;
        normself[i] = r * r;
    }
}

// single-block exclusive scan of cnt -> rowptr (and fill copy)
__global__ void k_scan(const int* __restrict__ cnt, int* rowptr, int* fill, int n, int e) {
    __shared__ int sh[1024];
    const int tid = threadIdx.x;           // blockDim = 1024
    const int CH = (n + 1023) / 1024;
    int base = tid * CH;
    int lim = min(base + CH, n);
    int local = 0;
    for (int i = base; i < lim; i++) local += cnt[i];
    sh[tid] = local;
    __syncthreads();
    // Hillis-Steele inclusive scan
    for (int off = 1; off < 1024; off <<= 1) {
        int v = (tid >= off) ? sh[tid - off] : 0;
        __syncthreads();
        sh[tid] += v;
        __syncthreads();
    }
    int running = sh[tid] - local;   // exclusive offset
    for (int i = base; i < lim; i++) {
        rowptr[i] = running;
        fill[i] = running;
        running += cnt[i];
    }
    if (tid == 0) rowptr[n] = e;
}

__global__ void k_place(const int* __restrict__ src, const int* __restrict__ dst,
                        const float* __restrict__ w, const float* __restrict__ dinv,
                        int* fill, int2* csr, int e) {
    int i = blockIdx.x * blockDim.x + threadIdx.x;
    if (i < e) {
        int s = src[i], d = dst[i];
        float nm = dinv[s] * w[i] * dinv[d];
        int pos = atomicAdd(fill + d, 1);
        csr[pos] = make_int2(s, __float_as_int(nm));
    }
}

__global__ void k_zero_stats() {
    int i = threadIdx.x;
    if (i < 256) g_stats[i] = 0.0f;
}

// ---------------- tf32 helpers ------------------------------------------------
__device__ __forceinline__ uint32_t f2tf32(float f) {
    uint32_t r;
    asm("cvt.rna.tf32.f32 %0, %1;" : "=r"(r) : "f"(f));
    return r;
}

__device__ __forceinline__ void mma_tf32(float c[4], uint32_t a0, uint32_t a1,
                                         uint32_t a2, uint32_t a3,
                                         uint32_t b0, uint32_t b1) {
    asm volatile(
        "mma.sync.aligned.m16n8k8.row.col.f32.tf32.tf32.f32 "
        "{%0,%1,%2,%3}, {%4,%5,%6,%7}, {%8,%9}, {%0,%1,%2,%3};"
        : "+f"(c[0]), "+f"(c[1]), "+f"(c[2]), "+f"(c[3])
        : "r"(a0), "r"(a1), "r"(a2), "r"(a3), "r"(b0), "r"(b1));
}

// ---------------- tf32 tensor-core GEMM: C[M,NOUT] = A[M,K] @ B[K,NOUT] -------
// Optional fused BatchNorm(scale/shift from g_scale/g_shift) + ReLU on A load.
template <int K, int NOUT, bool BN>
__global__ void k_gemm_tc(const float* __restrict__ A, const float* __restrict__ B,
                          float* __restrict__ C, int M) {
    constexpr int BM = 128;
    constexpr int SA = K + 4;
    constexpr int SB = NOUT + 8;
    constexpr int NT = NOUT / 8;

    extern __shared__ uint32_t sm[];
    uint32_t* As = sm;              // [BM][SA]
    uint32_t* Bs = sm + BM * SA;    // [K][SB]

    const int tid = threadIdx.x;
    const int lane = tid & 31;
    const int warp = tid >> 5;
    const int rowBase = blockIdx.x * BM;

    for (int l = tid; l < K * NOUT / 4; l += 256) {
        int r = l / (NOUT / 4);
        int c4 = l % (NOUT / 4);
        float4 v = *reinterpret_cast<const float4*>(B + (size_t)r * NOUT + c4 * 4);
        uint32_t* p = Bs + r * SB + c4 * 4;
        p[0] = f2tf32(v.x); p[1] = f2tf32(v.y); p[2] = f2tf32(v.z); p[3] = f2tf32(v.w);
    }
    for (int l = tid; l < BM * K / 4; l += 256) {
        int r = l / (K / 4);
        int c4 = l % (K / 4);
        int gr = rowBase + r;
        float4 v = make_float4(0.f, 0.f, 0.f, 0.f);
        if (gr < M) v = *reinterpret_cast<const float4*>(A + (size_t)gr * K + c4 * 4);
        if (BN) {
            float4 sc = *reinterpret_cast<const float4*>(g_scale + c4 * 4);
            float4 sh = *reinterpret_cast<const float4*>(g_shift + c4 * 4);
            v.x = fmaxf(fmaf(v.x, sc.x, sh.x), 0.f);
            v.y = fmaxf(fmaf(v.y, sc.y, sh.y), 0.f);
            v.z = fmaxf(fmaf(v.z, sc.z, sh.z), 0.f);
            v.w = fmaxf(fmaf(v.w, sc.w, sh.w), 0.f);
        }
        uint32_t* p = As + r * SA + c4 * 4;
        p[0] = f2tf32(v.x); p[1] = f2tf32(v.y); p[2] = f2tf32(v.z); p[3] = f2tf32(v.w);
    }
    __syncthreads();

    float acc[NT][4];
#pragma unroll
    for (int nt = 0; nt < NT; nt++) {
        acc[nt][0] = 0.f; acc[nt][1] = 0.f; acc[nt][2] = 0.f; acc[nt][3] = 0.f;
    }

    const int r0 = (warp << 4) + (lane >> 2);
    const int c0 = lane & 3;
    const int bcol = lane >> 2;

#pragma unroll 4
    for (int kk = 0; kk < K; kk += 8) {
        uint32_t a0 = As[r0 * SA + kk + c0];
        uint32_t a1 = As[(r0 + 8) * SA + kk + c0];
        uint32_t a2 = As[r0 * SA + kk + c0 + 4];
        uint32_t a3 = As[(r0 + 8) * SA + kk + c0 + 4];
#pragma unroll
        for (int nt = 0; nt < NT; nt++) {
            uint32_t b0 = Bs[(kk + c0) * SB + nt * 8 + bcol];
            uint32_t b1 = Bs[(kk + c0 + 4) * SB + nt * 8 + bcol];
            mma_tf32(acc[nt], a0, a1, a2, a3, b0, b1);
        }
    }

    int gr0 = rowBase + r0;
    int gr1 = gr0 + 8;
    if (gr0 < M) {
#pragma unroll
        for (int nt = 0; nt < NT; nt++)
            *reinterpret_cast<float2*>(C + (size_t)gr0 * NOUT + nt * 8 + c0 * 2) =
                make_float2(acc[nt][0], acc[nt][1]);
    }
    if (gr1 < M) {
#pragma unroll
        for (int nt = 0; nt < NT; nt++)
            *reinterpret_cast<float2*>(C + (size_t)gr1 * NOUT + nt * 8 + c0 * 2) =
                make_float2(acc[nt][2], acc[nt][3]);
    }
}

// ---------------- pull aggregation: out[d] = ns*h2[d] + b + sum(norm*h2[src]) -
// Fused BN sum/sumsq accumulation (STATS).
template <int FEAT, bool STATS>
__global__ void k_agg(const int* __restrict__ rowptr, const int2* __restrict__ csr,
                      const float* __restrict__ h2, const float* __restrict__ bias,
                      const float* __restrict__ normself, float* __restrict__ out,
                      int n) {
    constexpr int LPN = FEAT / 4;     // lanes per node
    constexpr int NPW = 32 / LPN;     // nodes per warp
    const int lane = threadIdx.x & 31;
    const int warpG = (blockIdx.x * blockDim.x + threadIdx.x) >> 5;
    const int nWarps = (gridDim.x * blockDim.x) >> 5;
    const int sub = lane / LPN;
    const int fc = lane % LPN;

    float4 bb = *reinterpret_cast<const float4*>(bias + fc * 4);

    float s0 = 0.f, s1 = 0.f, s2 = 0.f, s3 = 0.f;
    float q0 = 0.f, q1 = 0.f, q2 = 0.f, q3 = 0.f;

    for (int node = warpG * NPW + sub; node < n; node += nWarps * NPW) {
        int beg = rowptr[node];
        int end = rowptr[node + 1];
        float ns = normself[node];
        float4 h = *reinterpret_cast<const float4*>(h2 + (size_t)node * FEAT + fc * 4);
        float4 acc = make_float4(fmaf(ns, h.x, bb.x), fmaf(ns, h.y, bb.y),
                                 fmaf(ns, h.z, bb.z), fmaf(ns, h.w, bb.w));
        int e = beg;
        for (; e + 1 < end; e += 2) {
            int2 m0 = csr[e];
            int2 m1 = csr[e + 1];
            float4 v0 = *reinterpret_cast<const float4*>(h2 + (size_t)m0.x * FEAT + fc * 4);
            float4 v1 = *reinterpret_cast<const float4*>(h2 + (size_t)m1.x * FEAT + fc * 4);
            float n0 = __int_as_float(m0.y);
            float n1 = __int_as_float(m1.y);
            acc.x = fmaf(n0, v0.x, acc.x); acc.x = fmaf(n1, v1.x, acc.x);
            acc.y = fmaf(n0, v0.y, acc.y); acc.y = fmaf(n1, v1.y, acc.y);
            acc.z = fmaf(n0, v0.z, acc.z); acc.z = fmaf(n1, v1.z, acc.z);
            acc.w = fmaf(n0, v0.w, acc.w); acc.w = fmaf(n1, v1.w, acc.w);
        }
        if (e < end) {
            int2 m0 = csr[e];
            float4 v0 = *reinterpret_cast<const float4*>(h2 + (size_t)m0.x * FEAT + fc * 4);
            float n0 = __int_as_float(m0.y);
            acc.x = fmaf(n0, v0.x, acc.x);
            acc.y = fmaf(n0, v0.y, acc.y);
            acc.z = fmaf(n0, v0.z, acc.z);
            acc.w = fmaf(n0, v0.w, acc.w);
        }
        *reinterpret_cast<float4*>(out + (size_t)node * FEAT + fc * 4) = acc;
        if (STATS) {
            s0 += acc.x; s1 += acc.y; s2 += acc.z; s3 += acc.w;
            q0 = fmaf(acc.x, acc.x, q0); q1 = fmaf(acc.y, acc.y, q1);
            q2 = fmaf(acc.z, acc.z, q2); q3 = fmaf(acc.w, acc.w, q3);
        }
    }

    if (STATS) {
        // reduce across subwarps (lanes sharing the same fc)
#pragma unroll
        for (int off = 16; off >= LPN; off >>= 1) {
            s0 += __shfl_down_sync(0xffffffffu, s0, off);
            s1 += __shfl_down_sync(0xffffffffu, s1, off);
            s2 += __shfl_down_sync(0xffffffffu, s2, off);
            s3 += __shfl_down_sync(0xffffffffu, s3, off);
            q0 += __shfl_down_sync(0xffffffffu, q0, off);
            q1 += __shfl_down_sync(0xffffffffu, q1, off);
            q2 += __shfl_down_sync(0xffffffffu, q2, off);
            q3 += __shfl_down_sync(0xffffffffu, q3, off);
        }
        __shared__ float sh_s[8][FEAT];
        __shared__ float sh_q[8][FEAT];
        const int wid = threadIdx.x >> 5;
        if (lane < LPN) {
            sh_s[wid][fc * 4 + 0] = s0; sh_s[wid][fc * 4 + 1] = s1;
            sh_s[wid][fc * 4 + 2] = s2; sh_s[wid][fc * 4 + 3] = s3;
            sh_q[wid][fc * 4 + 0] = q0; sh_q[wid][fc * 4 + 1] = q1;
            sh_q[wid][fc * 4 + 2] = q2; sh_q[wid][fc * 4 + 3] = q3;
        }
        __syncthreads();
        int tid = threadIdx.x;
        if (tid < FEAT) {
            float a = 0.f, b = 0.f;
#pragma unroll
            for (int w = 0; w < 8; w++) { a += sh_s[w][tid]; b += sh_q[w][tid]; }
            atomicAdd(&g_stats[tid], a);
            atomicAdd(&g_stats[128 + tid], b);
        }
    }
}

// ---------------- BN finalize ---------------------------------------------------
template <int FEAT>
__global__ void k_bn_finalize(const float* __restrict__ gamma, const float* __restrict__ beta,
                              float invN) {
    int f = threadIdx.x;
    if (f < FEAT) {
        float s = g_stats[f];
        float q = g_stats[128 + f];
        float mean = s * invN;
        float var = q * invN - mean * mean;
        float sc = gamma[f] * rsqrtf(var + EPS);
        g_scale[f] = sc;
        g_shift[f] = beta[f] - mean * sc;
    }
}

// ---------------- host orchestration -----------------------------------------
static inline int cdiv(int a, int b) { return (a + b - 1) / b; }

extern "C" void kernel_launch(void* const* d_in, const int* in_sizes, int n_in,
                              void* d_out, int out_size) {
    const float* x      = (const float*)d_in[0];
    const int*   src    = (const int*)d_in[1];
    const int*   dst    = (const int*)d_in[2];
    const float* weight = (const float*)d_in[3];
    const float* W1 = (const float*)d_in[4];
    const float* b1 = (const float*)d_in[5];
    const float* ga1 = (const float*)d_in[6];
    const float* be1 = (const float*)d_in[7];
    const float* W2 = (const float*)d_in[8];
    const float* b2 = (const float*)d_in[9];
    const float* ga2 = (const float*)d_in[10];
    const float* be2 = (const float*)d_in[11];
    const float* W3 = (const float*)d_in[12];
    const float* b3 = (const float*)d_in[13];

    const int N = in_sizes[0] / 128;
    const int E = in_sizes[1];
    float* outp = (float*)d_out;

    void *p_deg, *p_cnt, *p_fill, *p_rowptr, *p_csr, *p_dinv, *p_ns, *p_h2, *p_out;
    cudaGetSymbolAddress(&p_deg, g_deg);
    cudaGetSymbolAddress(&p_cnt, g_cnt);
    cudaGetSymbolAddress(&p_fill, g_fill);
    cudaGetSymbolAddress(&p_rowptr, g_rowptr);
    cudaGetSymbolAddress(&p_csr, g_csr);
    cudaGetSymbolAddress(&p_dinv, g_dinv);
    cudaGetSymbolAddress(&p_ns, g_normself);
    cudaGetSymbolAddress(&p_h2, g_h2);
    cudaGetSymbolAddress(&p_out, g_out);
    float* deg = (float*)p_deg;
    int* cnt = (int*)p_cnt;
    int* fill = (int*)p_fill;
    int* rowptr = (int*)p_rowptr;
    int2* csr = (int2*)p_csr;
    float* dinv = (float*)p_dinv;
    float* normself = (float*)p_ns;
    float* h2 = (float*)p_h2;
    float* agg = (float*)p_out;

    const float invN = 1.0f / (float)N;

    const int smem1 = (128 * (128 + 4) + 128 * (128 + 8)) * 4;
    const int smem2 = (128 * (128 + 4) + 128 * (64 + 8)) * 4;
    const int smem3 = (128 * (64 + 4) + 64 * (32 + 8)) * 4;
    cudaFuncSetAttribute(k_gemm_tc<128, 128, false>,
                         cudaFuncAttributeMaxDynamicSharedMemorySize, smem1);
    cudaFuncSetAttribute(k_gemm_tc<128, 64, true>,
                         cudaFuncAttributeMaxDynamicSharedMemorySize, smem2);
    cudaFuncSetAttribute(k_gemm_tc<64, 32, true>,
                         cudaFuncAttributeMaxDynamicSharedMemorySize, smem3);

    // --- CSR + normalization precompute (once, reused by all layers) ---
    k_init<<<cdiv(N, 256), 256>>>(deg, cnt, N);
    k_prep_edge<<<cdiv(E, 256), 256>>>(dst, weight, deg, cnt, E);
    k_dinv<<<cdiv(N, 256), 256>>>(deg, dinv, normself, N);
    k_scan<<<1, 1024>>>(cnt, rowptr, fill, N, E);
    k_place<<<cdiv(E, 256), 256>>>(src, dst, weight, dinv, fill, csr, E);
    k_zero_stats<<<1, 256>>>();

    const int gemmGrid = cdiv(N, 128);
    const int aggGrid = 1184;   // 8 blocks/SM

    // ---------------- Layer 1: 128 -> 128 ----------------
    k_gemm_tc<128, 128, false><<<gemmGrid, 256, smem1>>>(x, W1, h2, N);
    k_agg<128, true><<<aggGrid, 256>>>(rowptr, csr, h2, b1, normself, agg, N);
    k_bn_finalize<128><<<1, 128>>>(ga1, be1, invN);
    k_zero_stats<<<1, 256>>>();

    // ---------------- Layer 2: 128 -> 64 (BN+ReLU fused into GEMM A load) ---
    k_gemm_tc<128, 64, true><<<gemmGrid, 256, smem2>>>(agg, W2, h2, N);
    k_agg<64, true><<<aggGrid, 256>>>(rowptr, csr, h2, b2, normself, agg, N);
    k_bn_finalize<64><<<1, 64>>>(ga2, be2, invN);

    // ---------------- Layer 3: 64 -> 32 (writes d_out) ----------------
    k_gemm_tc<64, 32, true><<<gemmGrid, 256, smem3>>>(agg, W3, h2, N);
    k_agg<32, false><<<aggGrid, 256>>>(rowptr, csr, h2, b3, normself, outp, N);
}

// round 4
// speedup vs baseline: 1.9351x; 1.9351x over previous
#include <cuda_runtime.h>
#include <cuda_bf16.h>
#include <cstdint>

#define EPS 1e-5f

static constexpr int MAX_N = 50048;    // nodes (actual 50000)
static constexpr int MAX_E = 600064;   // edges (actual 600000)

// ---------------- scratch (device globals; no allocation allowed) ------------
__device__ float  g_deg[MAX_N];
__device__ int    g_cnt[MAX_N];
__device__ int    g_fill[MAX_N];
__device__ int    g_rowptr[MAX_N + 1];
__device__ int2   g_csr[MAX_E];        // (src, norm-bits)
__device__ float  g_dinv[MAX_N];
__device__ float  g_normself[MAX_N];
__device__ float4 g_h2[MAX_N * 32];    // GEMM output (up to 128 f/node)
__device__ float4 g_out[MAX_N * 32];   // aggregation output
__device__ float  g_stats[256];        // [0..128) sum, [128..256) sumsq
__device__ int    g_bsum[64];
__device__ int    g_boff[64];
__device__ __align__(16) float g_scale[128];
__device__ __align__(16) float g_shift[128];

// ---------------- prep kernels ------------------------------------------------
__global__ void k_init(float* deg, int* cnt, int n) {
    int i = blockIdx.x * blockDim.x + threadIdx.x;
    if (i < n) { deg[i] = 1.0f; cnt[i] = 0; }   // self loop weight 1
}

__global__ void k_prep_edge(const int* __restrict__ dst, const float* __restrict__ w,
                            float* deg, int* cnt, int e) {
    int i = blockIdx.x * blockDim.x + threadIdx.x;
    if (i < e) {
        int d = dst[i];
        atomicAdd(deg + d, w[i]);
        atomicAdd(cnt + d, 1);
    }
}

__global__ void k_dinv(const float* __restrict__ deg, float* dinv, float* normself, int n) {
    int i = blockIdx.x * blockDim.x + threadIdx.x;
    if (i < n) {
        float d = deg[i];
        float r = (d > 0.0f) ? rsqrtf(d) : 0.0f;
        dinv[i] = r;
        normself[i] = r * r;
    }
}

// ---- 3-phase parallel scan: cnt -> rowptr/fill (2048 elems per block) ----
__global__ void k_scan_block(const int* __restrict__ cnt, int* bsum, int n) {
    __shared__ int wsum[8];
    int base = blockIdx.x * 2048 + threadIdx.x * 8;
    int s = 0;
#pragma unroll
    for (int i = 0; i < 8; i++) {
        int idx = base + i;
        if (idx < n) s += cnt[idx];
    }
#pragma unroll
    for (int o = 16; o; o >>= 1) s += __shfl_down_sync(0xffffffffu, s, o);
    if ((threadIdx.x & 31) == 0) wsum[threadIdx.x >> 5] = s;
    __syncthreads();
    if (threadIdx.x == 0) {
        int t = 0;
#pragma unroll
        for (int w = 0; w < 8; w++) t += wsum[w];
        bsum[blockIdx.x] = t;
    }
}

__global__ void k_scan_top(const int* __restrict__ bsum, int* boff, int g,
                           int* rowptr, int n, int e) {
    // one warp; g <= 32
    int lane = threadIdx.x;
    int v = (lane < g) ? bsum[lane] : 0;
    int inc = v;
#pragma unroll
    for (int o = 1; o < 32; o <<= 1) {
        int t = __shfl_up_sync(0xffffffffu, inc, o);
        if (lane >= o) inc += t;
    }
    if (lane < g) boff[lane] = inc - v;   // exclusive
    if (lane == 0) rowptr[n] = e;
}

__global__ void k_scan_final(const int* __restrict__ cnt, const int* __restrict__ boff,
                             int* rowptr, int* fill, int n) {
    __shared__ int tsum[256];
    int tbase = blockIdx.x * 2048 + threadIdx.x * 8;
    int v[8];
    int s = 0;
#pragma unroll
    for (int i = 0; i < 8; i++) {
        int idx = tbase + i;
        v[i] = (idx < n) ? cnt[idx] : 0;
        s += v[i];
    }
    tsum[threadIdx.x] = s;
    __syncthreads();
    for (int off = 1; off < 256; off <<= 1) {
        int t = (threadIdx.x >= off) ? tsum[threadIdx.x - off] : 0;
        __syncthreads();
        tsum[threadIdx.x] += t;
        __syncthreads();
    }
    int run = boff[blockIdx.x] + tsum[threadIdx.x] - s;   // exclusive within grid
#pragma unroll
    for (int i = 0; i < 8; i++) {
        int idx = tbase + i;
        if (idx < n) {
            rowptr[idx] = run;
            fill[idx] = run;
            run += v[i];
        }
    }
}

__global__ void k_place(const int* __restrict__ src, const int* __restrict__ dst,
                        const float* __restrict__ w, const float* __restrict__ dinv,
                        int* fill, int2* csr, int e) {
    int i = blockIdx.x * blockDim.x + threadIdx.x;
    if (i < e) {
        int s = src[i], d = dst[i];
        float nm = dinv[s] * w[i] * dinv[d];
        int pos = atomicAdd(fill + d, 1);
        csr[pos] = make_int2(s, __float_as_int(nm));
    }
}

__global__ void k_zero_stats() {
    int i = threadIdx.x;
    if (i < 256) g_stats[i] = 0.0f;
}

// ---------------- tf32 helpers ------------------------------------------------
__device__ __forceinline__ uint32_t f2tf32(float f) {
    uint32_t r;
    asm("cvt.rna.tf32.f32 %0, %1;" : "=r"(r) : "f"(f));
    return r;
}

__device__ __forceinline__ void mma_tf32(float c[4], uint32_t a0, uint32_t a1,
                                         uint32_t a2, uint32_t a3,
                                         uint32_t b0, uint32_t b1) {
    asm volatile(
        "mma.sync.aligned.m16n8k8.row.col.f32.tf32.tf32.f32 "
        "{%0,%1,%2,%3}, {%4,%5,%6,%7}, {%8,%9}, {%0,%1,%2,%3};"
        : "+f"(c[0]), "+f"(c[1]), "+f"(c[2]), "+f"(c[3])
        : "r"(a0), "r"(a1), "r"(a2), "r"(a3), "r"(b0), "r"(b1));
}

// ---------------- tf32 tensor-core GEMM: C[M,NOUT] = A[M,K] @ B[K,NOUT] -------
template <int K, int NOUT, bool BN>
__global__ void k_gemm_tc(const float* __restrict__ A, const float* __restrict__ B,
                          float* __restrict__ C, int M) {
    constexpr int BM = 128;
    constexpr int SA = K + 4;
    constexpr int SB = NOUT + 8;
    constexpr int NT = NOUT / 8;

    extern __shared__ uint32_t sm[];
    uint32_t* As = sm;              // [BM][SA]
    uint32_t* Bs = sm + BM * SA;    // [K][SB]

    const int tid = threadIdx.x;
    const int lane = tid & 31;
    const int warp = tid >> 5;
    const int rowBase = blockIdx.x * BM;

    for (int l = tid; l < K * NOUT / 4; l += 256) {
        int r = l / (NOUT / 4);
        int c4 = l % (NOUT / 4);
        float4 v = *reinterpret_cast<const float4*>(B + (size_t)r * NOUT + c4 * 4);
        uint32_t* p = Bs + r * SB + c4 * 4;
        p[0] = f2tf32(v.x); p[1] = f2tf32(v.y); p[2] = f2tf32(v.z); p[3] = f2tf32(v.w);
    }
    for (int l = tid; l < BM * K / 4; l += 256) {
        int r = l / (K / 4);
        int c4 = l % (K / 4);
        int gr = rowBase + r;
        float4 v = make_float4(0.f, 0.f, 0.f, 0.f);
        if (gr < M) v = *reinterpret_cast<const float4*>(A + (size_t)gr * K + c4 * 4);
        if (BN) {
            float4 sc = *reinterpret_cast<const float4*>(g_scale + c4 * 4);
            float4 sh = *reinterpret_cast<const float4*>(g_shift + c4 * 4);
            v.x = fmaxf(fmaf(v.x, sc.x, sh.x), 0.f);
            v.y = fmaxf(fmaf(v.y, sc.y, sh.y), 0.f);
            v.z = fmaxf(fmaf(v.z, sc.z, sh.z), 0.f);
            v.w = fmaxf(fmaf(v.w, sc.w, sh.w), 0.f);
        }
        uint32_t* p = As + r * SA + c4 * 4;
        p[0] = f2tf32(v.x); p[1] = f2tf32(v.y); p[2] = f2tf32(v.z); p[3] = f2tf32(v.w);
    }
    __syncthreads();

    float acc[NT][4];
#pragma unroll
    for (int nt = 0; nt < NT; nt++) {
        acc[nt][0] = 0.f; acc[nt][1] = 0.f; acc[nt][2] = 0.f; acc[nt][3] = 0.f;
    }

    const int r0 = (warp << 4) + (lane >> 2);
    const int c0 = lane & 3;
    const int bcol = lane >> 2;

#pragma unroll 4
    for (int kk = 0; kk < K; kk += 8) {
        uint32_t a0 = As[r0 * SA + kk + c0];
        uint32_t a1 = As[(r0 + 8) * SA + kk + c0];
        uint32_t a2 = As[r0 * SA + kk + c0 + 4];
        uint32_t a3 = As[(r0 + 8) * SA + kk + c0 + 4];
#pragma unroll
        for (int nt = 0; nt < NT; nt++) {
            uint32_t b0 = Bs[(kk + c0) * SB + nt * 8 + bcol];
            uint32_t b1 = Bs[(kk + c0 + 4) * SB + nt * 8 + bcol];
            mma_tf32(acc[nt], a0, a1, a2, a3, b0, b1);
        }
    }

    int gr0 = rowBase + r0;
    int gr1 = gr0 + 8;
    if (gr0 < M) {
#pragma unroll
        for (int nt = 0; nt < NT; nt++)
            *reinterpret_cast<float2*>(C + (size_t)gr0 * NOUT + nt * 8 + c0 * 2) =
                make_float2(acc[nt][0], acc[nt][1]);
    }
    if (gr1 < M) {
#pragma unroll
        for (int nt = 0; nt < NT; nt++)
            *reinterpret_cast<float2*>(C + (size_t)gr1 * NOUT + nt * 8 + c0 * 2) =
                make_float2(acc[nt][2], acc[nt][3]);
    }
}

// ---------------- pull aggregation (4-edge unroll, dual accumulators) --------
template <int FEAT, bool STATS>
__global__ void k_agg(const int* __restrict__ rowptr, const int2* __restrict__ csr,
                      const float* __restrict__ h2, const float* __restrict__ bias,
                      const float* __restrict__ normself, float* __restrict__ out,
                      int n) {
    constexpr int LPN = FEAT / 4;     // lanes per node
    constexpr int NPW = 32 / LPN;     // nodes per warp
    const int lane = threadIdx.x & 31;
    const int warpG = (blockIdx.x * blockDim.x + threadIdx.x) >> 5;
    const int nWarps = (gridDim.x * blockDim.x) >> 5;
    const int sub = lane / LPN;
    const int fc = lane % LPN;

    float4 bb = *reinterpret_cast<const float4*>(bias + fc * 4);

    float s0 = 0.f, s1 = 0.f, s2 = 0.f, s3 = 0.f;
    float q0 = 0.f, q1 = 0.f, q2 = 0.f, q3 = 0.f;

    for (int node = warpG * NPW + sub; node < n; node += nWarps * NPW) {
        int beg = rowptr[node];
        int end = rowptr[node + 1];
        float ns = normself[node];
        float4 h = *reinterpret_cast<const float4*>(h2 + (size_t)node * FEAT + fc * 4);
        float4 accA = make_float4(fmaf(ns, h.x, bb.x), fmaf(ns, h.y, bb.y),
                                  fmaf(ns, h.z, bb.z), fmaf(ns, h.w, bb.w));
        float4 accB = make_float4(0.f, 0.f, 0.f, 0.f);
        int e = beg;
        for (; e + 3 < end; e += 4) {
            int2 m0 = csr[e];
            int2 m1 = csr[e + 1];
            int2 m2 = csr[e + 2];
            int2 m3 = csr[e + 3];
            float4 v0 = *reinterpret_cast<const float4*>(h2 + (size_t)m0.x * FEAT + fc * 4);
            float4 v1 = *reinterpret_cast<const float4*>(h2 + (size_t)m1.x * FEAT + fc * 4);
            float4 v2 = *reinterpret_cast<const float4*>(h2 + (size_t)m2.x * FEAT + fc * 4);
            float4 v3 = *reinterpret_cast<const float4*>(h2 + (size_t)m3.x * FEAT + fc * 4);
            float n0 = __int_as_float(m0.y), n1 = __int_as_float(m1.y);
            float n2 = __int_as_float(m2.y), n3 = __int_as_float(m3.y);
            accA.x = fmaf(n0, v0.x, accA.x); accB.x = fmaf(n1, v1.x, accB.x);
            accA.y = fmaf(n0, v0.y, accA.y); accB.y = fmaf(n1, v1.y, accB.y);
            accA.z = fmaf(n0, v0.z, accA.z); accB.z = fmaf(n1, v1.z, accB.z);
            accA.w = fmaf(n0, v0.w, accA.w); accB.w = fmaf(n1, v1.w, accB.w);
            accA.x = fmaf(n2, v2.x, accA.x); accB.x = fmaf(n3, v3.x, accB.x);
            accA.y = fmaf(n2, v2.y, accA.y); accB.y = fmaf(n3, v3.y, accB.y);
            accA.z = fmaf(n2, v2.z, accA.z); accB.z = fmaf(n3, v3.z, accB.z);
            accA.w = fmaf(n2, v2.w, accA.w); accB.w = fmaf(n3, v3.w, accB.w);
        }
        for (; e < end; e++) {
            int2 m0 = csr[e];
            float4 v0 = *reinterpret_cast<const float4*>(h2 + (size_t)m0.x * FEAT + fc * 4);
            float n0 = __int_as_float(m0.y);
            accA.x = fmaf(n0, v0.x, accA.x);
            accA.y = fmaf(n0, v0.y, accA.y);
            accA.z = fmaf(n0, v0.z, accA.z);
            accA.w = fmaf(n0, v0.w, accA.w);
        }
        float4 acc = make_float4(accA.x + accB.x, accA.y + accB.y,
                                 accA.z + accB.z, accA.w + accB.w);
        *reinterpret_cast<float4*>(out + (size_t)node * FEAT + fc * 4) = acc;
        if (STATS) {
            s0 += acc.x; s1 += acc.y; s2 += acc.z; s3 += acc.w;
            q0 = fmaf(acc.x, acc.x, q0); q1 = fmaf(acc.y, acc.y, q1);
            q2 = fmaf(acc.z, acc.z, q2); q3 = fmaf(acc.w, acc.w, q3);
        }
    }

    if (STATS) {
#pragma unroll
        for (int off = 16; off >= LPN; off >>= 1) {
            s0 += __shfl_down_sync(0xffffffffu, s0, off);
            s1 += __shfl_down_sync(0xffffffffu, s1, off);
            s2 += __shfl_down_sync(0xffffffffu, s2, off);
            s3 += __shfl_down_sync(0xffffffffu, s3, off);
            q0 += __shfl_down_sync(0xffffffffu, q0, off);
            q1 += __shfl_down_sync(0xffffffffu, q1, off);
            q2 += __shfl_down_sync(0xffffffffu, q2, off);
            q3 += __shfl_down_sync(0xffffffffu, q3, off);
        }
        __shared__ float sh_s[8][FEAT];
        __shared__ float sh_q[8][FEAT];
        const int wid = threadIdx.x >> 5;
        if (lane < LPN) {
            sh_s[wid][fc * 4 + 0] = s0; sh_s[wid][fc * 4 + 1] = s1;
            sh_s[wid][fc * 4 + 2] = s2; sh_s[wid][fc * 4 + 3] = s3;
            sh_q[wid][fc * 4 + 0] = q0; sh_q[wid][fc * 4 + 1] = q1;
            sh_q[wid][fc * 4 + 2] = q2; sh_q[wid][fc * 4 + 3] = q3;
        }
        __syncthreads();
        int tid = threadIdx.x;
        if (tid < FEAT) {
            float a = 0.f, b = 0.f;
#pragma unroll
            for (int w = 0; w < 8; w++) { a += sh_s[w][tid]; b += sh_q[w][tid]; }
            atomicAdd(&g_stats[tid], a);
            atomicAdd(&g_stats[128 + tid], b);
        }
    }
}

// ---------------- BN finalize (reads stats, zeroes them for next layer) -------
template <int FEAT>
__global__ void k_bn_finalize(const float* __restrict__ gamma, const float* __restrict__ beta,
                              float invN) {
    int f = threadIdx.x;
    if (f < FEAT) {
        float s = g_stats[f];
        float q = g_stats[128 + f];
        g_stats[f] = 0.0f;
        g_stats[128 + f] = 0.0f;
        float mean = s * invN;
        float var = q * invN - mean * mean;
        float sc = gamma[f] * rsqrtf(var + EPS);
        g_scale[f] = sc;
        g_shift[f] = beta[f] - mean * sc;
    }
}

// ---------------- host orchestration -----------------------------------------
static inline int cdiv(int a, int b) { return (a + b - 1) / b; }

extern "C" void kernel_launch(void* const* d_in, const int* in_sizes, int n_in,
                              void* d_out, int out_size) {
    const float* x      = (const float*)d_in[0];
    const int*   src    = (const int*)d_in[1];
    const int*   dst    = (const int*)d_in[2];
    const float* weight = (const float*)d_in[3];
    const float* W1 = (const float*)d_in[4];
    const float* b1 = (const float*)d_in[5];
    const float* ga1 = (const float*)d_in[6];
    const float* be1 = (const float*)d_in[7];
    const float* W2 = (const float*)d_in[8];
    const float* b2 = (const float*)d_in[9];
    const float* ga2 = (const float*)d_in[10];
    const float* be2 = (const float*)d_in[11];
    const float* W3 = (const float*)d_in[12];
    const float* b3 = (const float*)d_in[13];

    const int N = in_sizes[0] / 128;
    const int E = in_sizes[1];
    float* outp = (float*)d_out;

    void *p_deg, *p_cnt, *p_fill, *p_rowptr, *p_csr, *p_dinv, *p_ns, *p_h2, *p_out;
    void *p_bsum, *p_boff;
    cudaGetSymbolAddress(&p_deg, g_deg);
    cudaGetSymbolAddress(&p_cnt, g_cnt);
    cudaGetSymbolAddress(&p_fill, g_fill);
    cudaGetSymbolAddress(&p_rowptr, g_rowptr);
    cudaGetSymbolAddress(&p_csr, g_csr);
    cudaGetSymbolAddress(&p_dinv, g_dinv);
    cudaGetSymbolAddress(&p_ns, g_normself);
    cudaGetSymbolAddress(&p_h2, g_h2);
    cudaGetSymbolAddress(&p_out, g_out);
    cudaGetSymbolAddress(&p_bsum, g_bsum);
    cudaGetSymbolAddress(&p_boff, g_boff);
    float* deg = (float*)p_deg;
    int* cnt = (int*)p_cnt;
    int* fill = (int*)p_fill;
    int* rowptr = (int*)p_rowptr;
    int2* csr = (int2*)p_csr;
    float* dinv = (float*)p_dinv;
    float* normself = (float*)p_ns;
    float* h2 = (float*)p_h2;
    float* agg = (float*)p_out;
    int* bsum = (int*)p_bsum;
    int* boff = (int*)p_boff;

    const float invN = 1.0f / (float)N;

    const int smem1 = (128 * (128 + 4) + 128 * (128 + 8)) * 4;
    const int smem2 = (128 * (128 + 4) + 128 * (64 + 8)) * 4;
    const int smem3 = (128 * (64 + 4) + 64 * (32 + 8)) * 4;
    cudaFuncSetAttribute(k_gemm_tc<128, 128, false>,
                         cudaFuncAttributeMaxDynamicSharedMemorySize, smem1);
    cudaFuncSetAttribute(k_gemm_tc<128, 64, true>,
                         cudaFuncAttributeMaxDynamicSharedMemorySize, smem2);
    cudaFuncSetAttribute(k_gemm_tc<64, 32, true>,
                         cudaFuncAttributeMaxDynamicSharedMemorySize, smem3);

    // --- CSR + normalization precompute (once, reused by all layers) ---
    const int scanGrid = cdiv(N, 2048);   // 25 blocks for N=50000
    k_init<<<cdiv(N, 256), 256>>>(deg, cnt, N);
    k_prep_edge<<<cdiv(E, 256), 256>>>(dst, weight, deg, cnt, E);
    k_dinv<<<cdiv(N, 256), 256>>>(deg, dinv, normself, N);
    k_scan_block<<<scanGrid, 256>>>(cnt, bsum, N);
    k_scan_top<<<1, 32>>>(bsum, boff, scanGrid, rowptr, N, E);
    k_scan_final<<<scanGrid, 256>>>(cnt, boff, rowptr, fill, N);
    k_place<<<cdiv(E, 256), 256>>>(src, dst, weight, dinv, fill, csr, E);
    k_zero_stats<<<1, 256>>>();

    const int gemmGrid = cdiv(N, 128);
    const int aggGrid = 1184;   // 8 blocks/SM

    // ---------------- Layer 1: 128 -> 128 ----------------
    k_gemm_tc<128, 128, false><<<gemmGrid, 256, smem1>>>(x, W1, h2, N);
    k_agg<128, true><<<aggGrid, 256>>>(rowptr, csr, h2, b1, normself, agg, N);
    k_bn_finalize<128><<<1, 128>>>(ga1, be1, invN);

    // ---------------- Layer 2: 128 -> 64 (BN+ReLU fused into GEMM A load) ---
    k_gemm_tc<128, 64, true><<<gemmGrid, 256, smem2>>>(agg, W2, h2, N);
    k_agg<64, true><<<aggGrid, 256>>>(rowptr, csr, h2, b2, normself, agg, N);
    k_bn_finalize<64><<<1, 64>>>(ga2, be2, invN);

    // ---------------- Layer 3: 64 -> 32 (writes d_out) ----------------
    k_gemm_tc<64, 32, true><<<gemmGrid, 256, smem3>>>(agg, W3, h2, N);
    k_agg<32, false><<<aggGrid, 256>>>(rowptr, csr, h2, b3, normself, outp, N);
}

// round 6
// speedup vs baseline: 2.0668x; 1.0680x over previous
#include <cuda_runtime.h>
#include <cuda_bf16.h>
#include <cstdint>

#define EPS 1e-5f

static constexpr int MAX_N = 50048;    // nodes (actual 50000)
static constexpr int MAX_E = 600064;   // edges (actual 600000)

// ---------------- scratch (device globals; no allocation allowed) ------------
__device__ float  g_deg[MAX_N];
__device__ int    g_cnt[MAX_N];
__device__ int    g_fill[MAX_N];
__device__ int    g_rowptr[MAX_N + 1];
__device__ int2   g_csr[MAX_E];        // (src, norm-bits)
__device__ float  g_dinv[MAX_N];
__device__ float  g_normself[MAX_N];
__device__ float4 g_h2[MAX_N * 32];    // GEMM output (up to 128 f/node)
__device__ float4 g_out[MAX_N * 32];   // aggregation output
__device__ float  g_stats[384];        // L1: [0:128)sum [128:256)sq ; L2: [256:320)sum [320:384)sq
__device__ int    g_bsum[64];
__device__ int    g_boff[64];

// ---------------- prep kernels ------------------------------------------------
__global__ void k_init(float* deg, int* cnt, float* stats, int n) {
    int i = blockIdx.x * blockDim.x + threadIdx.x;
    if (i < n) { deg[i] = 1.0f; cnt[i] = 0; }   // self loop weight 1
    if (i < 384) stats[i] = 0.0f;               // zero ALL stats (both layers)
}

__global__ void k_prep_edge(const int* __restrict__ dst, const float* __restrict__ w,
                            float* deg, int* cnt, int e) {
    int i = blockIdx.x * blockDim.x + threadIdx.x;
    if (i < e) {
        int d = dst[i];
        atomicAdd(deg + d, w[i]);
        atomicAdd(cnt + d, 1);
    }
}

// block sums for scan + dinv/normself computation fused (deg is final here)
__global__ void k_scan_block(const int* __restrict__ cnt, const float* __restrict__ deg,
                             int* bsum, float* dinv, float* normself, int n) {
    __shared__ int wsum[8];
    int base = blockIdx.x * 2048 + threadIdx.x * 8;
    int s = 0;
#pragma unroll
    for (int i = 0; i < 8; i++) {
        int idx = base + i;
        if (idx < n) {
            s += cnt[idx];
            float d = deg[idx];
            float r = (d > 0.0f) ? rsqrtf(d) : 0.0f;
            dinv[idx] = r;
            normself[idx] = r * r;
        }
    }
#pragma unroll
    for (int o = 16; o; o >>= 1) s += __shfl_down_sync(0xffffffffu, s, o);
    if ((threadIdx.x & 31) == 0) wsum[threadIdx.x >> 5] = s;
    __syncthreads();
    if (threadIdx.x == 0) {
        int t = 0;
#pragma unroll
        for (int w = 0; w < 8; w++) t += wsum[w];
        bsum[blockIdx.x] = t;
    }
}

__global__ void k_scan_top(const int* __restrict__ bsum, int* boff, int g,
                           int* rowptr, int n, int e) {
    int lane = threadIdx.x;
    int v = (lane < g) ? bsum[lane] : 0;
    int inc = v;
#pragma unroll
    for (int o = 1; o < 32; o <<= 1) {
        int t = __shfl_up_sync(0xffffffffu, inc, o);
        if (lane >= o) inc += t;
    }
    if (lane < g) boff[lane] = inc - v;   // exclusive
    if (lane == 0) rowptr[n] = e;
}

__global__ void k_scan_final(const int* __restrict__ cnt, const int* __restrict__ boff,
                             int* rowptr, int* fill, int n) {
    __shared__ int tsum[256];
    int tbase = blockIdx.x * 2048 + threadIdx.x * 8;
    int v[8];
    int s = 0;
#pragma unroll
    for (int i = 0; i < 8; i++) {
        int idx = tbase + i;
        v[i] = (idx < n) ? cnt[idx] : 0;
        s += v[i];
    }
    tsum[threadIdx.x] = s;
    __syncthreads();
    for (int off = 1; off < 256; off <<= 1) {
        int t = (threadIdx.x >= off) ? tsum[threadIdx.x - off] : 0;
        __syncthreads();
        tsum[threadIdx.x] += t;
        __syncthreads();
    }
    int run = boff[blockIdx.x] + tsum[threadIdx.x] - s;
#pragma unroll
    for (int i = 0; i < 8; i++) {
        int idx = tbase + i;
        if (idx < n) {
            rowptr[idx] = run;
            fill[idx] = run;
            run += v[i];
        }
    }
}

__global__ void k_place(const int* __restrict__ src, const int* __restrict__ dst,
                        const float* __restrict__ w, const float* __restrict__ dinv,
                        int* fill, int2* csr, int e) {
    int i = blockIdx.x * blockDim.x + threadIdx.x;
    if (i < e) {
        int s = src[i], d = dst[i];
        float nm = dinv[s] * w[i] * dinv[d];
        int pos = atomicAdd(fill + d, 1);
        csr[pos] = make_int2(s, __float_as_int(nm));
    }
}

// ---------------- tf32 helpers ------------------------------------------------
__device__ __forceinline__ uint32_t f2tf32(float f) {
    uint32_t r;
    asm("cvt.rna.tf32.f32 %0, %1;" : "=r"(r) : "f"(f));
    return r;
}

__device__ __forceinline__ void mma_tf32(float c[4], uint32_t a0, uint32_t a1,
                                         uint32_t a2, uint32_t a3,
                                         uint32_t b0, uint32_t b1) {
    asm volatile(
        "mma.sync.aligned.m16n8k8.row.col.f32.tf32.tf32.f32 "
        "{%0,%1,%2,%3}, {%4,%5,%6,%7}, {%8,%9}, {%0,%1,%2,%3};"
        : "+f"(c[0]), "+f"(c[1]), "+f"(c[2]), "+f"(c[3])
        : "r"(a0), "r"(a1), "r"(a2), "r"(a3), "r"(b0), "r"(b1));
}

// ---------------- tf32 tensor-core GEMM with inline BN(+ReLU) on A ------------
template <int K, int NOUT, bool BN>
__global__ void k_gemm_tc(const float* __restrict__ A, const float* __restrict__ B,
                          float* __restrict__ C, int M,
                          const float* __restrict__ gamma, const float* __restrict__ beta,
                          const float* __restrict__ stats, float invN) {
    constexpr int BM = 128;
    constexpr int SA = K + 4;
    constexpr int SB = NOUT + 8;
    constexpr int NT = NOUT / 8;

    extern __shared__ uint32_t sm[];
    uint32_t* As = sm;              // [BM][SA]
    uint32_t* Bs = sm + BM * SA;    // [K][SB]
    __shared__ float sscale[K > 0 ? K : 1];
    __shared__ float sshift[K > 0 ? K : 1];

    const int tid = threadIdx.x;
    const int lane = tid & 31;
    const int warp = tid >> 5;
    const int rowBase = blockIdx.x * BM;

    if (BN && tid < K) {
        float s = stats[tid];
        float q = stats[K + tid];
        float mean = s * invN;
        float var = q * invN - mean * mean;
        float sc = gamma[tid] * rsqrtf(var + EPS);
        sscale[tid] = sc;
        sshift[tid] = beta[tid] - mean * sc;
    }

    for (int l = tid; l < K * NOUT / 4; l += 256) {
        int r = l / (NOUT / 4);
        int c4 = l % (NOUT / 4);
        float4 v = *reinterpret_cast<const float4*>(B + (size_t)r * NOUT + c4 * 4);
        uint32_t* p = Bs + r * SB + c4 * 4;
        p[0] = f2tf32(v.x); p[1] = f2tf32(v.y); p[2] = f2tf32(v.z); p[3] = f2tf32(v.w);
    }
    if (BN) __syncthreads();   // sscale/sshift visible before A staging

    for (int l = tid; l < BM * K / 4; l += 256) {
        int r = l / (K / 4);
        int c4 = l % (K / 4);
        int gr = rowBase + r;
        float4 v = make_float4(0.f, 0.f, 0.f, 0.f);
        if (gr < M) v = *reinterpret_cast<const float4*>(A + (size_t)gr * K + c4 * 4);
        if (BN) {
            v.x = fmaxf(fmaf(v.x, sscale[c4 * 4 + 0], sshift[c4 * 4 + 0]), 0.f);
            v.y = fmaxf(fmaf(v.y, sscale[c4 * 4 + 1], sshift[c4 * 4 + 1]), 0.f);
            v.z = fmaxf(fmaf(v.z, sscale[c4 * 4 + 2], sshift[c4 * 4 + 2]), 0.f);
            v.w = fmaxf(fmaf(v.w, sscale[c4 * 4 + 3], sshift[c4 * 4 + 3]), 0.f);
        }
        uint32_t* p = As + r * SA + c4 * 4;
        p[0] = f2tf32(v.x); p[1] = f2tf32(v.y); p[2] = f2tf32(v.z); p[3] = f2tf32(v.w);
    }
    __syncthreads();

    float acc[NT][4];
#pragma unroll
    for (int nt = 0; nt < NT; nt++) {
        acc[nt][0] = 0.f; acc[nt][1] = 0.f; acc[nt][2] = 0.f; acc[nt][3] = 0.f;
    }

    const int r0 = (warp << 4) + (lane >> 2);
    const int c0 = lane & 3;
    const int bcol = lane >> 2;

#pragma unroll 4
    for (int kk = 0; kk < K; kk += 8) {
        uint32_t a0 = As[r0 * SA + kk + c0];
        uint32_t a1 = As[(r0 + 8) * SA + kk + c0];
        uint32_t a2 = As[r0 * SA + kk + c0 + 4];
        uint32_t a3 = As[(r0 + 8) * SA + kk + c0 + 4];
#pragma unroll
        for (int nt = 0; nt < NT; nt++) {
            uint32_t b0 = Bs[(kk + c0) * SB + nt * 8 + bcol];
            uint32_t b1 = Bs[(kk + c0 + 4) * SB + nt * 8 + bcol];
            mma_tf32(acc[nt], a0, a1, a2, a3, b0, b1);
        }
    }

    int gr0 = rowBase + r0;
    int gr1 = gr0 + 8;
    if (gr0 < M) {
#pragma unroll
        for (int nt = 0; nt < NT; nt++)
            *reinterpret_cast<float2*>(C + (size_t)gr0 * NOUT + nt * 8 + c0 * 2) =
                make_float2(acc[nt][0], acc[nt][1]);
    }
    if (gr1 < M) {
#pragma unroll
        for (int nt = 0; nt < NT; nt++)
            *reinterpret_cast<float2*>(C + (size_t)gr1 * NOUT + nt * 8 + c0 * 2) =
                make_float2(acc[nt][2], acc[nt][3]);
    }
}

// ---------------- pull aggregation (8-edge unroll, 4 accumulator sets) --------
template <int FEAT, bool STATS>
__global__ void k_agg(const int* __restrict__ rowptr, const int2* __restrict__ csr,
                      const float* __restrict__ h2, const float* __restrict__ bias,
                      const float* __restrict__ normself, float* __restrict__ out,
                      float* stats, int n) {
    constexpr int LPN = FEAT / 4;     // lanes per node
    constexpr int NPW = 32 / LPN;     // nodes per warp
    const int lane = threadIdx.x & 31;
    const int warpG = (blockIdx.x * blockDim.x + threadIdx.x) >> 5;
    const int nWarps = (gridDim.x * blockDim.x) >> 5;
    const int sub = lane / LPN;
    const int fc = lane % LPN;

    float4 bb = *reinterpret_cast<const float4*>(bias + fc * 4);

    float s0 = 0.f, s1 = 0.f, s2 = 0.f, s3 = 0.f;
    float q0 = 0.f, q1 = 0.f, q2 = 0.f, q3 = 0.f;

    for (int node = warpG * NPW + sub; node < n; node += nWarps * NPW) {
        int beg = rowptr[node];
        int end = rowptr[node + 1];
        float ns = normself[node];
        float4 h = *reinterpret_cast<const float4*>(h2 + (size_t)node * FEAT + fc * 4);
        float4 aA = make_float4(fmaf(ns, h.x, bb.x), fmaf(ns, h.y, bb.y),
                                fmaf(ns, h.z, bb.z), fmaf(ns, h.w, bb.w));
        float4 aB = make_float4(0.f, 0.f, 0.f, 0.f);
        float4 aC = make_float4(0.f, 0.f, 0.f, 0.f);
        float4 aD = make_float4(0.f, 0.f, 0.f, 0.f);
        int e = beg;
        for (; e + 7 < end; e += 8) {
            int2 m0 = csr[e],     m1 = csr[e + 1], m2 = csr[e + 2], m3 = csr[e + 3];
            int2 m4 = csr[e + 4], m5 = csr[e + 5], m6 = csr[e + 6], m7 = csr[e + 7];
            float4 v0 = *reinterpret_cast<const float4*>(h2 + (size_t)m0.x * FEAT + fc * 4);
            float4 v1 = *reinterpret_cast<const float4*>(h2 + (size_t)m1.x * FEAT + fc * 4);
            float4 v2 = *reinterpret_cast<const float4*>(h2 + (size_t)m2.x * FEAT + fc * 4);
            float4 v3 = *reinterpret_cast<const float4*>(h2 + (size_t)m3.x * FEAT + fc * 4);
            float4 v4 = *reinterpret_cast<const float4*>(h2 + (size_t)m4.x * FEAT + fc * 4);
            float4 v5 = *reinterpret_cast<const float4*>(h2 + (size_t)m5.x * FEAT + fc * 4);
            float4 v6 = *reinterpret_cast<const float4*>(h2 + (size_t)m6.x * FEAT + fc * 4);
            float4 v7 = *reinterpret_cast<const float4*>(h2 + (size_t)m7.x * FEAT + fc * 4);
            float n0 = __int_as_float(m0.y), n1 = __int_as_float(m1.y);
            float n2 = __int_as_float(m2.y), n3 = __int_as_float(m3.y);
            float n4 = __int_as_float(m4.y), n5 = __int_as_float(m5.y);
            float n6 = __int_as_float(m6.y), n7 = __int_as_float(m7.y);
            aA.x = fmaf(n0, v0.x, aA.x); aB.x = fmaf(n1, v1.x, aB.x);
            aC.x = fmaf(n2, v2.x, aC.x); aD.x = fmaf(n3, v3.x, aD.x);
            aA.y = fmaf(n0, v0.y, aA.y); aB.y = fmaf(n1, v1.y, aB.y);
            aC.y = fmaf(n2, v2.y, aC.y); aD.y = fmaf(n3, v3.y, aD.y);
            aA.z = fmaf(n0, v0.z, aA.z); aB.z = fmaf(n1, v1.z, aB.z);
            aC.z = fmaf(n2, v2.z, aC.z); aD.z = fmaf(n3, v3.z, aD.z);
            aA.w = fmaf(n0, v0.w, aA.w); aB.w = fmaf(n1, v1.w, aB.w);
            aC.w = fmaf(n2, v2.w, aC.w); aD.w = fmaf(n3, v3.w, aD.w);
            aA.x = fmaf(n4, v4.x, aA.x); aB.x = fmaf(n5, v5.x, aB.x);
            aC.x = fmaf(n6, v6.x, aC.x); aD.x = fmaf(n7, v7.x, aD.x);
            aA.y = fmaf(n4, v4.y, aA.y); aB.y = fmaf(n5, v5.y, aB.y);
            aC.y = fmaf(n6, v6.y, aC.y); aD.y = fmaf(n7, v7.y, aD.y);
            aA.z = fmaf(n4, v4.z, aA.z); aB.z = fmaf(n5, v5.z, aB.z);
            aC.z = fmaf(n6, v6.z, aC.z); aD.z = fmaf(n7, v7.z, aD.z);
            aA.w = fmaf(n4, v4.w, aA.w); aB.w = fmaf(n5, v5.w, aB.w);
            aC.w = fmaf(n6, v6.w, aC.w); aD.w = fmaf(n7, v7.w, aD.w);
        }
        for (; e + 1 < end; e += 2) {
            int2 m0 = csr[e], m1 = csr[e + 1];
            float4 v0 = *reinterpret_cast<const float4*>(h2 + (size_t)m0.x * FEAT + fc * 4);
            float4 v1 = *reinterpret_cast<const float4*>(h2 + (size_t)m1.x * FEAT + fc * 4);
            float n0 = __int_as_float(m0.y), n1 = __int_as_float(m1.y);
            aA.x = fmaf(n0, v0.x, aA.x); aB.x = fmaf(n1, v1.x, aB.x);
            aA.y = fmaf(n0, v0.y, aA.y); aB.y = fmaf(n1, v1.y, aB.y);
            aA.z = fmaf(n0, v0.z, aA.z); aB.z = fmaf(n1, v1.z, aB.z);
            aA.w = fmaf(n0, v0.w, aA.w); aB.w = fmaf(n1, v1.w, aB.w);
        }
        if (e < end) {
            int2 m0 = csr[e];
            float4 v0 = *reinterpret_cast<const float4*>(h2 + (size_t)m0.x * FEAT + fc * 4);
            float n0 = __int_as_float(m0.y);
            aA.x = fmaf(n0, v0.x, aA.x);
            aA.y = fmaf(n0, v0.y, aA.y);
            aA.z = fmaf(n0, v0.z, aA.z);
            aA.w = fmaf(n0, v0.w, aA.w);
        }
        float4 acc = make_float4((aA.x + aB.x) + (aC.x + aD.x),
                                 (aA.y + aB.y) + (aC.y + aD.y),
                                 (aA.z + aB.z) + (aC.z + aD.z),
                                 (aA.w + aB.w) + (aC.w + aD.w));
        *reinterpret_cast<float4*>(out + (size_t)node * FEAT + fc * 4) = acc;
        if (STATS) {
            s0 += acc.x; s1 += acc.y; s2 += acc.z; s3 += acc.w;
            q0 = fmaf(acc.x, acc.x, q0); q1 = fmaf(acc.y, acc.y, q1);
            q2 = fmaf(acc.z, acc.z, q2); q3 = fmaf(acc.w, acc.w, q3);
        }
    }

    if (STATS) {
#pragma unroll
        for (int off = 16; off >= LPN; off >>= 1) {
            s0 += __shfl_down_sync(0xffffffffu, s0, off);
            s1 += __shfl_down_sync(0xffffffffu, s1, off);
            s2 += __shfl_down_sync(0xffffffffu, s2, off);
            s3 += __shfl_down_sync(0xffffffffu, s3, off);
            q0 += __shfl_down_sync(0xffffffffu, q0, off);
            q1 += __shfl_down_sync(0xffffffffu, q1, off);
            q2 += __shfl_down_sync(0xffffffffu, q2, off);
            q3 += __shfl_down_sync(0xffffffffu, q3, off);
        }
        __shared__ float sh_s[8][FEAT];
        __shared__ float sh_q[8][FEAT];
        const int wid = threadIdx.x >> 5;
        if (lane < LPN) {
            sh_s[wid][fc * 4 + 0] = s0; sh_s[wid][fc * 4 + 1] = s1;
            sh_s[wid][fc * 4 + 2] = s2; sh_s[wid][fc * 4 + 3] = s3;
            sh_q[wid][fc * 4 + 0] = q0; sh_q[wid][fc * 4 + 1] = q1;
            sh_q[wid][fc * 4 + 2] = q2; sh_q[wid][fc * 4 + 3] = q3;
        }
        __syncthreads();
        int tid = threadIdx.x;
        if (tid < FEAT) {
            float a = 0.f, b = 0.f;
#pragma unroll
            for (int w = 0; w < 8; w++) { a += sh_s[w][tid]; b += sh_q[w][tid]; }
            atomicAdd(&stats[tid], a);
            atomicAdd(&stats[FEAT + tid], b);
        }
    }
}

// ---------------- host orchestration -----------------------------------------
static inline int cdiv(int a, int b) { return (a + b - 1) / b; }

extern "C" void kernel_launch(void* const* d_in, const int* in_sizes, int n_in,
                              void* d_out, int out_size) {
    const float* x      = (const float*)d_in[0];
    const int*   src    = (const int*)d_in[1];
    const int*   dst    = (const int*)d_in[2];
    const float* weight = (const float*)d_in[3];
    const float* W1 = (const float*)d_in[4];
    const float* b1 = (const float*)d_in[5];
    const float* ga1 = (const float*)d_in[6];
    const float* be1 = (const float*)d_in[7];
    const float* W2 = (const float*)d_in[8];
    const float* b2 = (const float*)d_in[9];
    const float* ga2 = (const float*)d_in[10];
    const float* be2 = (const float*)d_in[11];
    const float* W3 = (const float*)d_in[12];
    const float* b3 = (const float*)d_in[13];

    const int N = in_sizes[0] / 128;
    const int E = in_sizes[1];
    float* outp = (float*)d_out;

    void *p_deg, *p_cnt, *p_fill, *p_rowptr, *p_csr, *p_dinv, *p_ns, *p_h2, *p_out;
    void *p_bsum, *p_boff, *p_stats;
    cudaGetSymbolAddress(&p_deg, g_deg);
    cudaGetSymbolAddress(&p_cnt, g_cnt);
    cudaGetSymbolAddress(&p_fill, g_fill);
    cudaGetSymbolAddress(&p_rowptr, g_rowptr);
    cudaGetSymbolAddress(&p_csr, g_csr);
    cudaGetSymbolAddress(&p_dinv, g_dinv);
    cudaGetSymbolAddress(&p_ns, g_normself);
    cudaGetSymbolAddress(&p_h2, g_h2);
    cudaGetSymbolAddress(&p_out, g_out);
    cudaGetSymbolAddress(&p_bsum, g_bsum);
    cudaGetSymbolAddress(&p_boff, g_boff);
    cudaGetSymbolAddress(&p_stats, g_stats);
    float* deg = (float*)p_deg;
    int* cnt = (int*)p_cnt;
    int* fill = (int*)p_fill;
    int* rowptr = (int*)p_rowptr;
    int2* csr = (int2*)p_csr;
    float* dinv = (float*)p_dinv;
    float* normself = (float*)p_ns;
    float* h2 = (float*)p_h2;
    float* agg = (float*)p_out;
    int* bsum = (int*)p_bsum;
    int* boff = (int*)p_boff;
    float* stats1 = (float*)p_stats;        // layer1: 256 floats
    float* stats2 = (float*)p_stats + 256;  // layer2: 128 floats

    const float invN = 1.0f / (float)N;

    const int smem1 = (128 * (128 + 4) + 128 * (128 + 8)) * 4;
    const int smem2 = (128 * (128 + 4) + 128 * (64 + 8)) * 4;
    const int smem3 = (128 * (64 + 4) + 64 * (32 + 8)) * 4;
    cudaFuncSetAttribute(k_gemm_tc<128, 128, false>,
                         cudaFuncAttributeMaxDynamicSharedMemorySize, smem1);
    cudaFuncSetAttribute(k_gemm_tc<128, 64, true>,
                         cudaFuncAttributeMaxDynamicSharedMemorySize, smem2);
    cudaFuncSetAttribute(k_gemm_tc<64, 32, true>,
                         cudaFuncAttributeMaxDynamicSharedMemorySize, smem3);

    // --- CSR + normalization precompute (once, reused by all layers) ---
    const int scanGrid = cdiv(N, 2048);   // 25 blocks for N=50000
    k_init<<<cdiv(N, 256), 256>>>(deg, cnt, stats1, N);
    k_prep_edge<<<cdiv(E, 256), 256>>>(dst, weight, deg, cnt, E);
    k_scan_block<<<scanGrid, 256>>>(cnt, deg, bsum, dinv, normself, N);
    k_scan_top<<<1, 32>>>(bsum, boff, scanGrid, rowptr, N, E);
    k_scan_final<<<scanGrid, 256>>>(cnt, boff, rowptr, fill, N);
    k_place<<<cdiv(E, 256), 256>>>(src, dst, weight, dinv, fill, csr, E);

    const int gemmGrid = cdiv(N, 128);
    const int aggGrid = 1184;   // 8 blocks/SM

    // ---------------- Layer 1: 128 -> 128 ----------------
    k_gemm_tc<128, 128, false><<<gemmGrid, 256, smem1>>>(x, W1, h2, N,
                                                         nullptr, nullptr, nullptr, invN);
    k_agg<128, true><<<aggGrid, 256>>>(rowptr, csr, h2, b1, normself, agg, stats1, N);

    // ---------------- Layer 2: 128 -> 64 (BN+ReLU fused into GEMM) ----------
    k_gemm_tc<128, 64, true><<<gemmGrid, 256, smem2>>>(agg, W2, h2, N,
                                                       ga1, be1, stats1, invN);
    k_agg<64, true><<<aggGrid, 256>>>(rowptr, csr, h2, b2, normself, agg, stats2, N);

    // ---------------- Layer 3: 64 -> 32 (writes d_out) ----------------
    k_gemm_tc<64, 32, true><<<gemmGrid, 256, smem3>>>(agg, W3, h2, N,
                                                      ga2, be2, stats2, invN);
    k_agg<32, false><<<aggGrid, 256>>>(rowptr, csr, h2, b3, normself, outp, nullptr, N);
}

// round 7
// speedup vs baseline: 2.1675x; 1.0487x over previous
#include <cuda_runtime.h>
#include <cuda_bf16.h>
#include <cstdint>

#define EPS 1e-5f

static constexpr int MAX_N = 50048;    // nodes (actual 50000)
static constexpr int MAX_E = 600064;   // edges (actual 600000)

// ---------------- scratch (device globals; no allocation allowed) ------------
__device__ float  g_deg[MAX_N];
__device__ int    g_cnt[MAX_N];
__device__ int    g_fill[MAX_N];
__device__ int    g_rowptr[MAX_N + 1];
__device__ int2   g_csr[MAX_E];        // (src, norm-bits)
__device__ float  g_dinv[MAX_N];
__device__ float  g_normself[MAX_N];
__device__ float4 g_h2[MAX_N * 32];    // GEMM output (up to 128 f/node)
__device__ float4 g_out[MAX_N * 32];   // aggregation output
__device__ float  g_stats[384];        // L1: [0:128)sum [128:256)sq ; L2: [256:320)sum [320:384)sq
__device__ int    g_bsum[64];

// ---------------- prep kernels ------------------------------------------------
__global__ void k_init(float* deg, int* cnt, float* stats, int n) {
    int i = blockIdx.x * blockDim.x + threadIdx.x;
    if (i < n) { deg[i] = 1.0f; cnt[i] = 0; }   // self loop weight 1
    if (i < 384) stats[i] = 0.0f;               // zero ALL stats (both layers)
}

__global__ void k_prep_edge(const int* __restrict__ dst, const float* __restrict__ w,
                            float* deg, int* cnt, int e) {
    int i = blockIdx.x * blockDim.x + threadIdx.x;
    if (i < e) {
        int d = dst[i];
        atomicAdd(deg + d, w[i]);
        atomicAdd(cnt + d, 1);
    }
}

// block sums for scan + dinv/normself computation fused (deg is final here)
__global__ void k_scan_block(const int* __restrict__ cnt, const float* __restrict__ deg,
                             int* bsum, float* dinv, float* normself, int n) {
    __shared__ int wsum[8];
    int base = blockIdx.x * 2048 + threadIdx.x * 8;
    int s = 0;
#pragma unroll
    for (int i = 0; i < 8; i++) {
        int idx = base + i;
        if (idx < n) {
            s += cnt[idx];
            float d = deg[idx];
            float r = (d > 0.0f) ? rsqrtf(d) : 0.0f;
            dinv[idx] = r;
            normself[idx] = r * r;
        }
    }
#pragma unroll
    for (int o = 16; o; o >>= 1) s += __shfl_down_sync(0xffffffffu, s, o);
    if ((threadIdx.x & 31) == 0) wsum[threadIdx.x >> 5] = s;
    __syncthreads();
    if (threadIdx.x == 0) {
        int t = 0;
#pragma unroll
        for (int w = 0; w < 8; w++) t += wsum[w];
        bsum[blockIdx.x] = t;
    }
}

// scan_final with inline top-level prefix (sums bsum[0..blockIdx) serially)
__global__ void k_scan_final(const int* __restrict__ cnt, const int* __restrict__ bsum,
                             int* rowptr, int* fill, int n, int e) {
    __shared__ int tsum[256];
    __shared__ int blockOff;
    if (threadIdx.x == 0) {
        int off = 0;
        for (int b = 0; b < blockIdx.x; b++) off += bsum[b];
        blockOff = off;
        if (blockIdx.x == 0) rowptr[n] = e;
    }
    int tbase = blockIdx.x * 2048 + threadIdx.x * 8;
    int v[8];
    int s = 0;
#pragma unroll
    for (int i = 0; i < 8; i++) {
        int idx = tbase + i;
        v[i] = (idx < n) ? cnt[idx] : 0;
        s += v[i];
    }
    tsum[threadIdx.x] = s;
    __syncthreads();
    for (int off = 1; off < 256; off <<= 1) {
        int t = (threadIdx.x >= off) ? tsum[threadIdx.x - off] : 0;
        __syncthreads();
        tsum[threadIdx.x] += t;
        __syncthreads();
    }
    int run = blockOff + tsum[threadIdx.x] - s;
#pragma unroll
    for (int i = 0; i < 8; i++) {
        int idx = tbase + i;
        if (idx < n) {
            rowptr[idx] = run;
            fill[idx] = run;
            run += v[i];
        }
    }
}

__global__ void k_place(const int* __restrict__ src, const int* __restrict__ dst,
                        const float* __restrict__ w, const float* __restrict__ dinv,
                        int* fill, int2* csr, int e) {
    int i = blockIdx.x * blockDim.x + threadIdx.x;
    if (i < e) {
        int s = src[i], d = dst[i];
        float nm = dinv[s] * w[i] * dinv[d];
        int pos = atomicAdd(fill + d, 1);
        csr[pos] = make_int2(s, __float_as_int(nm));
    }
}

// ---------------- tf32 helpers ------------------------------------------------
__device__ __forceinline__ uint32_t f2tf32(float f) {
    uint32_t r;
    asm("cvt.rna.tf32.f32 %0, %1;" : "=r"(r) : "f"(f));
    return r;
}

__device__ __forceinline__ void mma_tf32(float c[4], uint32_t a0, uint32_t a1,
                                         uint32_t a2, uint32_t a3,
                                         uint32_t b0, uint32_t b1) {
    asm volatile(
        "mma.sync.aligned.m16n8k8.row.col.f32.tf32.tf32.f32 "
        "{%0,%1,%2,%3}, {%4,%5,%6,%7}, {%8,%9}, {%0,%1,%2,%3};"
        : "+f"(c[0]), "+f"(c[1]), "+f"(c[2]), "+f"(c[3])
        : "r"(a0), "r"(a1), "r"(a2), "r"(a3), "r"(b0), "r"(b1));
}

// ---------------- tf32 tensor-core GEMM with inline BN(+ReLU) on A ------------
template <int K, int NOUT, bool BN>
__global__ void k_gemm_tc(const float* __restrict__ A, const float* __restrict__ B,
                          float* __restrict__ C, int M,
                          const float* __restrict__ gamma, const float* __restrict__ beta,
                          const float* __restrict__ stats, float invN) {
    constexpr int BM = 128;
    constexpr int SA = K + 4;
    constexpr int SB = NOUT + 8;
    constexpr int NT = NOUT / 8;

    extern __shared__ uint32_t sm[];
    uint32_t* As = sm;              // [BM][SA]
    uint32_t* Bs = sm + BM * SA;    // [K][SB]
    __shared__ float sscale[K > 0 ? K : 1];
    __shared__ float sshift[K > 0 ? K : 1];

    const int tid = threadIdx.x;
    const int lane = tid & 31;
    const int warp = tid >> 5;
    const int rowBase = blockIdx.x * BM;

    if (BN && tid < K) {
        float s = stats[tid];
        float q = stats[K + tid];
        float mean = s * invN;
        float var = q * invN - mean * mean;
        float sc = gamma[tid] * rsqrtf(var + EPS);
        sscale[tid] = sc;
        sshift[tid] = beta[tid] - mean * sc;
    }

    for (int l = tid; l < K * NOUT / 4; l += 256) {
        int r = l / (NOUT / 4);
        int c4 = l % (NOUT / 4);
        float4 v = *reinterpret_cast<const float4*>(B + (size_t)r * NOUT + c4 * 4);
        uint32_t* p = Bs + r * SB + c4 * 4;
        p[0] = f2tf32(v.x); p[1] = f2tf32(v.y); p[2] = f2tf32(v.z); p[3] = f2tf32(v.w);
    }
    if (BN) __syncthreads();   // sscale/sshift visible before A staging

    for (int l = tid; l < BM * K / 4; l += 256) {
        int r = l / (K / 4);
        int c4 = l % (K / 4);
        int gr = rowBase + r;
        float4 v = make_float4(0.f, 0.f, 0.f, 0.f);
        if (gr < M) v = *reinterpret_cast<const float4*>(A + (size_t)gr * K + c4 * 4);
        if (BN) {
            v.x = fmaxf(fmaf(v.x, sscale[c4 * 4 + 0], sshift[c4 * 4 + 0]), 0.f);
            v.y = fmaxf(fmaf(v.y, sscale[c4 * 4 + 1], sshift[c4 * 4 + 1]), 0.f);
            v.z = fmaxf(fmaf(v.z, sscale[c4 * 4 + 2], sshift[c4 * 4 + 2]), 0.f);
            v.w = fmaxf(fmaf(v.w, sscale[c4 * 4 + 3], sshift[c4 * 4 + 3]), 0.f);
        }
        uint32_t* p = As + r * SA + c4 * 4;
        p[0] = f2tf32(v.x); p[1] = f2tf32(v.y); p[2] = f2tf32(v.z); p[3] = f2tf32(v.w);
    }
    __syncthreads();

    float acc[NT][4];
#pragma unroll
    for (int nt = 0; nt < NT; nt++) {
        acc[nt][0] = 0.f; acc[nt][1] = 0.f; acc[nt][2] = 0.f; acc[nt][3] = 0.f;
    }

    const int r0 = (warp << 4) + (lane >> 2);
    const int c0 = lane & 3;
    const int bcol = lane >> 2;

#pragma unroll 4
    for (int kk = 0; kk < K; kk += 8) {
        uint32_t a0 = As[r0 * SA + kk + c0];
        uint32_t a1 = As[(r0 + 8) * SA + kk + c0];
        uint32_t a2 = As[r0 * SA + kk + c0 + 4];
        uint32_t a3 = As[(r0 + 8) * SA + kk + c0 + 4];
#pragma unroll
        for (int nt = 0; nt < NT; nt++) {
            uint32_t b0 = Bs[(kk + c0) * SB + nt * 8 + bcol];
            uint32_t b1 = Bs[(kk + c0 + 4) * SB + nt * 8 + bcol];
            mma_tf32(acc[nt], a0, a1, a2, a3, b0, b1);
        }
    }

    int gr0 = rowBase + r0;
    int gr1 = gr0 + 8;
    if (gr0 < M) {
#pragma unroll
        for (int nt = 0; nt < NT; nt++)
            *reinterpret_cast<float2*>(C + (size_t)gr0 * NOUT + nt * 8 + c0 * 2) =
                make_float2(acc[nt][0], acc[nt][1]);
    }
    if (gr1 < M) {
#pragma unroll
        for (int nt = 0; nt < NT; nt++)
            *reinterpret_cast<float2*>(C + (size_t)gr1 * NOUT + nt * 8 + c0 * 2) =
                make_float2(acc[nt][2], acc[nt][3]);
    }
}

// ---------------- pull aggregation (8-edge unroll, 4 accumulator sets) --------
template <int FEAT, bool STATS>
__global__ void k_agg(const int* __restrict__ rowptr, const int2* __restrict__ csr,
                      const float* __restrict__ h2, const float* __restrict__ bias,
                      const float* __restrict__ normself, float* __restrict__ out,
                      float* stats, int n) {
    constexpr int LPN = FEAT / 4;     // lanes per node
    constexpr int NPW = 32 / LPN;     // nodes per warp
    const int lane = threadIdx.x & 31;
    const int warpG = (blockIdx.x * blockDim.x + threadIdx.x) >> 5;
    const int nWarps = (gridDim.x * blockDim.x) >> 5;
    const int sub = lane / LPN;
    const int fc = lane % LPN;

    float4 bb = *reinterpret_cast<const float4*>(bias + fc * 4);

    float s0 = 0.f, s1 = 0.f, s2 = 0.f, s3 = 0.f;
    float q0 = 0.f, q1 = 0.f, q2 = 0.f, q3 = 0.f;

    for (int node = warpG * NPW + sub; node < n; node += nWarps * NPW) {
        int beg = rowptr[node];
        int end = rowptr[node + 1];
        float ns = normself[node];
        float4 h = *reinterpret_cast<const float4*>(h2 + (size_t)node * FEAT + fc * 4);
        float4 aA = make_float4(fmaf(ns, h.x, bb.x), fmaf(ns, h.y, bb.y),
                                fmaf(ns, h.z, bb.z), fmaf(ns, h.w, bb.w));
        float4 aB = make_float4(0.f, 0.f, 0.f, 0.f);
        float4 aC = make_float4(0.f, 0.f, 0.f, 0.f);
        float4 aD = make_float4(0.f, 0.f, 0.f, 0.f);
        int e = beg;
        for (; e + 7 < end; e += 8) {
            int2 m0 = csr[e],     m1 = csr[e + 1], m2 = csr[e + 2], m3 = csr[e + 3];
            int2 m4 = csr[e + 4], m5 = csr[e + 5], m6 = csr[e + 6], m7 = csr[e + 7];
            float4 v0 = *reinterpret_cast<const float4*>(h2 + (size_t)m0.x * FEAT + fc * 4);
            float4 v1 = *reinterpret_cast<const float4*>(h2 + (size_t)m1.x * FEAT + fc * 4);
            float4 v2 = *reinterpret_cast<const float4*>(h2 + (size_t)m2.x * FEAT + fc * 4);
            float4 v3 = *reinterpret_cast<const float4*>(h2 + (size_t)m3.x * FEAT + fc * 4);
            float4 v4 = *reinterpret_cast<const float4*>(h2 + (size_t)m4.x * FEAT + fc * 4);
            float4 v5 = *reinterpret_cast<const float4*>(h2 + (size_t)m5.x * FEAT + fc * 4);
            float4 v6 = *reinterpret_cast<const float4*>(h2 + (size_t)m6.x * FEAT + fc * 4);
            float4 v7 = *reinterpret_cast<const float4*>(h2 + (size_t)m7.x * FEAT + fc * 4);
            float n0 = __int_as_float(m0.y), n1 = __int_as_float(m1.y);
            float n2 = __int_as_float(m2.y), n3 = __int_as_float(m3.y);
            float n4 = __int_as_float(m4.y), n5 = __int_as_float(m5.y);
            float n6 = __int_as_float(m6.y), n7 = __int_as_float(m7.y);
            aA.x = fmaf(n0, v0.x, aA.x); aB.x = fmaf(n1, v1.x, aB.x);
            aC.x = fmaf(n2, v2.x, aC.x); aD.x = fmaf(n3, v3.x, aD.x);
            aA.y = fmaf(n0, v0.y, aA.y); aB.y = fmaf(n1, v1.y, aB.y);
            aC.y = fmaf(n2, v2.y, aC.y); aD.y = fmaf(n3, v3.y, aD.y);
            aA.z = fmaf(n0, v0.z, aA.z); aB.z = fmaf(n1, v1.z, aB.z);
            aC.z = fmaf(n2, v2.z, aC.z); aD.z = fmaf(n3, v3.z, aD.z);
            aA.w = fmaf(n0, v0.w, aA.w); aB.w = fmaf(n1, v1.w, aB.w);
            aC.w = fmaf(n2, v2.w, aC.w); aD.w = fmaf(n3, v3.w, aD.w);
            aA.x = fmaf(n4, v4.x, aA.x); aB.x = fmaf(n5, v5.x, aB.x);
            aC.x = fmaf(n6, v6.x, aC.x); aD.x = fmaf(n7, v7.x, aD.x);
            aA.y = fmaf(n4, v4.y, aA.y); aB.y = fmaf(n5, v5.y, aB.y);
            aC.y = fmaf(n6, v6.y, aC.y); aD.y = fmaf(n7, v7.y, aD.y);
            aA.z = fmaf(n4, v4.z, aA.z); aB.z = fmaf(n5, v5.z, aB.z);
            aC.z = fmaf(n6, v6.z, aC.z); aD.z = fmaf(n7, v7.z, aD.z);
            aA.w = fmaf(n4, v4.w, aA.w); aB.w = fmaf(n5, v5.w, aB.w);
            aC.w = fmaf(n6, v6.w, aC.w); aD.w = fmaf(n7, v7.w, aD.w);
        }
        for (; e + 1 < end; e += 2) {
            int2 m0 = csr[e], m1 = csr[e + 1];
            float4 v0 = *reinterpret_cast<const float4*>(h2 + (size_t)m0.x * FEAT + fc * 4);
            float4 v1 = *reinterpret_cast<const float4*>(h2 + (size_t)m1.x * FEAT + fc * 4);
            float n0 = __int_as_float(m0.y), n1 = __int_as_float(m1.y);
            aA.x = fmaf(n0, v0.x, aA.x); aB.x = fmaf(n1, v1.x, aB.x);
            aA.y = fmaf(n0, v0.y, aA.y); aB.y = fmaf(n1, v1.y, aB.y);
            aA.z = fmaf(n0, v0.z, aA.z); aB.z = fmaf(n1, v1.z, aB.z);
            aA.w = fmaf(n0, v0.w, aA.w); aB.w = fmaf(n1, v1.w, aB.w);
        }
        if (e < end) {
            int2 m0 = csr[e];
            float4 v0 = *reinterpret_cast<const float4*>(h2 + (size_t)m0.x * FEAT + fc * 4);
            float n0 = __int_as_float(m0.y);
            aA.x = fmaf(n0, v0.x, aA.x);
            aA.y = fmaf(n0, v0.y, aA.y);
            aA.z = fmaf(n0, v0.z, aA.z);
            aA.w = fmaf(n0, v0.w, aA.w);
        }
        float4 acc = make_float4((aA.x + aB.x) + (aC.x + aD.x),
                                 (aA.y + aB.y) + (aC.y + aD.y),
                                 (aA.z + aB.z) + (aC.z + aD.z),
                                 (aA.w + aB.w) + (aC.w + aD.w));
        *reinterpret_cast<float4*>(out + (size_t)node * FEAT + fc * 4) = acc;
        if (STATS) {
            s0 += acc.x; s1 += acc.y; s2 += acc.z; s3 += acc.w;
            q0 = fmaf(acc.x, acc.x, q0); q1 = fmaf(acc.y, acc.y, q1);
            q2 = fmaf(acc.z, acc.z, q2); q3 = fmaf(acc.w, acc.w, q3);
        }
    }

    if (STATS) {
#pragma unroll
        for (int off = 16; off >= LPN; off >>= 1) {
            s0 += __shfl_down_sync(0xffffffffu, s0, off);
            s1 += __shfl_down_sync(0xffffffffu, s1, off);
            s2 += __shfl_down_sync(0xffffffffu, s2, off);
            s3 += __shfl_down_sync(0xffffffffu, s3, off);
            q0 += __shfl_down_sync(0xffffffffu, q0, off);
            q1 += __shfl_down_sync(0xffffffffu, q1, off);
            q2 += __shfl_down_sync(0xffffffffu, q2, off);
            q3 += __shfl_down_sync(0xffffffffu, q3, off);
        }
        __shared__ float sh_s[8][FEAT];
        __shared__ float sh_q[8][FEAT];
        const int wid = threadIdx.x >> 5;
        if (lane < LPN) {
            sh_s[wid][fc * 4 + 0] = s0; sh_s[wid][fc * 4 + 1] = s1;
            sh_s[wid][fc * 4 + 2] = s2; sh_s[wid][fc * 4 + 3] = s3;
            sh_q[wid][fc * 4 + 0] = q0; sh_q[wid][fc * 4 + 1] = q1;
            sh_q[wid][fc * 4 + 2] = q2; sh_q[wid][fc * 4 + 3] = q3;
        }
        __syncthreads();
        int tid = threadIdx.x;
        if (tid < FEAT) {
            float a = 0.f, b = 0.f;
#pragma unroll
            for (int w = 0; w < 8; w++) { a += sh_s[w][tid]; b += sh_q[w][tid]; }
            atomicAdd(&stats[tid], a);
            atomicAdd(&stats[FEAT + tid], b);
        }
    }
}

// ---------------- host orchestration -----------------------------------------
static inline int cdiv(int a, int b) { return (a + b - 1) / b; }

extern "C" void kernel_launch(void* const* d_in, const int* in_sizes, int n_in,
                              void* d_out, int out_size) {
    const float* x      = (const float*)d_in[0];
    const int*   src    = (const int*)d_in[1];
    const int*   dst    = (const int*)d_in[2];
    const float* weight = (const float*)d_in[3];
    const float* W1 = (const float*)d_in[4];
    const float* b1 = (const float*)d_in[5];
    const float* ga1 = (const float*)d_in[6];
    const float* be1 = (const float*)d_in[7];
    const float* W2 = (const float*)d_in[8];
    const float* b2 = (const float*)d_in[9];
    const float* ga2 = (const float*)d_in[10];
    const float* be2 = (const float*)d_in[11];
    const float* W3 = (const float*)d_in[12];
    const float* b3 = (const float*)d_in[13];

    const int N = in_sizes[0] / 128;
    const int E = in_sizes[1];
    float* outp = (float*)d_out;

    void *p_deg, *p_cnt, *p_fill, *p_rowptr, *p_csr, *p_dinv, *p_ns, *p_h2, *p_out;
    void *p_bsum, *p_stats;
    cudaGetSymbolAddress(&p_deg, g_deg);
    cudaGetSymbolAddress(&p_cnt, g_cnt);
    cudaGetSymbolAddress(&p_fill, g_fill);
    cudaGetSymbolAddress(&p_rowptr, g_rowptr);
    cudaGetSymbolAddress(&p_csr, g_csr);
    cudaGetSymbolAddress(&p_dinv, g_dinv);
    cudaGetSymbolAddress(&p_ns, g_normself);
    cudaGetSymbolAddress(&p_h2, g_h2);
    cudaGetSymbolAddress(&p_out, g_out);
    cudaGetSymbolAddress(&p_bsum, g_bsum);
    cudaGetSymbolAddress(&p_stats, g_stats);
    float* deg = (float*)p_deg;
    int* cnt = (int*)p_cnt;
    int* fill = (int*)p_fill;
    int* rowptr = (int*)p_rowptr;
    int2* csr = (int2*)p_csr;
    float* dinv = (float*)p_dinv;
    float* normself = (float*)p_ns;
    float* h2 = (float*)p_h2;
    float* agg = (float*)p_out;
    int* bsum = (int*)p_bsum;
    float* stats1 = (float*)p_stats;        // layer1: 256 floats
    float* stats2 = (float*)p_stats + 256;  // layer2: 128 floats

    const float invN = 1.0f / (float)N;

    const int smem1 = (128 * (128 + 4) + 128 * (128 + 8)) * 4;
    const int smem2 = (128 * (128 + 4) + 128 * (64 + 8)) * 4;
    const int smem3 = (128 * (64 + 4) + 64 * (32 + 8)) * 4;
    cudaFuncSetAttribute(k_gemm_tc<128, 128, false>,
                         cudaFuncAttributeMaxDynamicSharedMemorySize, smem1);
    cudaFuncSetAttribute(k_gemm_tc<128, 64, true>,
                         cudaFuncAttributeMaxDynamicSharedMemorySize, smem2);
    cudaFuncSetAttribute(k_gemm_tc<64, 32, true>,
                         cudaFuncAttributeMaxDynamicSharedMemorySize, smem3);

    // side stream + fork/join events (created per call; host-side objects only)
    cudaStream_t s2;
    cudaEvent_t evFork, evJoin;
    cudaStreamCreateWithFlags(&s2, cudaStreamNonBlocking);
    cudaEventCreateWithFlags(&evFork, cudaEventDisableTiming);
    cudaEventCreateWithFlags(&evJoin, cudaEventDisableTiming);

    const int scanGrid = cdiv(N, 2048);   // 25 blocks for N=50000
    const int gemmGrid = cdiv(N, 128);
    const int aggGrid = 1184;             // 8 blocks/SM

    // ---- fork: CSR/normalization prep on s2, concurrent with Layer-1 GEMM ----
    cudaEventRecord(evFork, 0);
    cudaStreamWaitEvent(s2, evFork, 0);

    k_init<<<cdiv(N, 256), 256, 0, s2>>>(deg, cnt, stats1, N);
    k_prep_edge<<<cdiv(E, 256), 256, 0, s2>>>(dst, weight, deg, cnt, E);
    k_scan_block<<<scanGrid, 256, 0, s2>>>(cnt, deg, bsum, dinv, normself, N);
    k_scan_final<<<scanGrid, 256, 0, s2>>>(cnt, bsum, rowptr, fill, N, E);
    k_place<<<cdiv(E, 256), 256, 0, s2>>>(src, dst, weight, dinv, fill, csr, E);
    cudaEventRecord(evJoin, s2);

    // Layer-1 GEMM on main stream (independent of prep)
    k_gemm_tc<128, 128, false><<<gemmGrid, 256, smem1>>>(x, W1, h2, N,
                                                         nullptr, nullptr, nullptr, invN);

    // ---- join: everything after needs both GEMM1 and the CSR ----
    cudaStreamWaitEvent(0, evJoin, 0);

    k_agg<128, true><<<aggGrid, 256>>>(rowptr, csr, h2, b1, normself, agg, stats1, N);

    k_gemm_tc<128, 64, true><<<gemmGrid, 256, smem2>>>(agg, W2, h2, N,
                                                       ga1, be1, stats1, invN);
    k_agg<64, true><<<aggGrid, 256>>>(rowptr, csr, h2, b2, normself, agg, stats2, N);

    k_gemm_tc<64, 32, true><<<gemmGrid, 256, smem3>>>(agg, W3, h2, N,
                                                      ga2, be2, stats2, invN);
    k_agg<32, false><<<aggGrid, 256>>>(rowptr, csr, h2, b3, normself, outp, nullptr, N);
}

// round 8
// speedup vs baseline: 2.2038x; 1.0168x over previous
#include <cuda_runtime.h>
#include <cuda_bf16.h>
#include <cstdint>

#define EPS 1e-5f

static constexpr int MAX_N = 50048;    // nodes (actual 50000)
static constexpr int MAX_E = 600064;   // edges (actual 600000)

// ---------------- scratch (device globals; no allocation allowed) ------------
__device__ float  g_deg[MAX_N];
__device__ int    g_cnt[MAX_N];
__device__ int    g_fill[MAX_N];
__device__ int    g_rowptr[MAX_N + 1];
__device__ int2   g_csr[MAX_E];        // (src, norm-bits)
__device__ float  g_dinv[MAX_N];
__device__ float  g_normself[MAX_N];
__device__ float4 g_h2[MAX_N * 32];    // GEMM output (up to 128 f/node)
__device__ float4 g_out[MAX_N * 32];   // aggregation output
__device__ float  g_stats[384];        // L1: [0:128)sum [128:256)sq ; L2: [256:320)sum [320:384)sq
__device__ unsigned long long g_scanstate[64];

// ---------------- PDL helpers --------------------------------------------------
__device__ __forceinline__ void pdl_wait() {
    asm volatile("griddepcontrol.wait;" ::: "memory");
}
__device__ __forceinline__ void pdl_trigger() {
    asm volatile("griddepcontrol.launch_dependents;" ::: "memory");
}

// ---------------- prep kernels ------------------------------------------------
__global__ void k_init(float* deg, int* cnt, float* stats, unsigned long long* state, int n) {
    int i = blockIdx.x * blockDim.x + threadIdx.x;
    if (i < n) { deg[i] = 1.0f; cnt[i] = 0; }   // self loop weight 1
    if (i < 384) stats[i] = 0.0f;               // zero ALL stats (both layers)
    if (i < 64) state[i] = 0ull;                // reset scan lookback state
}

__global__ void k_prep_edge(const int* __restrict__ dst, const float* __restrict__ w,
                            float* deg, int* cnt, int e) {
    int i = blockIdx.x * blockDim.x + threadIdx.x;
    if (i < e) {
        int d = dst[i];
        atomicAdd(deg + d, w[i]);
        atomicAdd(cnt + d, 1);
    }
}

// ---- fused single-pass scan (decoupled lookback) + dinv/normself -------------
__global__ void k_scan(const int* __restrict__ cnt, const float* __restrict__ deg,
                       float* dinv, float* normself, int* rowptr, int* fill,
                       volatile unsigned long long* state, int n, int e) {
    __shared__ int warpTot[8];
    __shared__ int blockOffSh;
    const int tid = threadIdx.x;
    const int lane = tid & 31;
    const int wid = tid >> 5;
    int tbase = blockIdx.x * 2048 + tid * 8;
    int v[8];
    int s = 0;
#pragma unroll
    for (int i = 0; i < 8; i++) {
        int idx = tbase + i;
        v[i] = (idx < n) ? cnt[idx] : 0;
        s += v[i];
        if (idx < n) {
            float d = deg[idx];
            float r = (d > 0.f) ? rsqrtf(d) : 0.f;
            dinv[idx] = r;
            normself[idx] = r * r;
        }
    }
    // warp inclusive scan of per-thread sums
    int inc = s;
#pragma unroll
    for (int o = 1; o < 32; o <<= 1) {
        int t = __shfl_up_sync(0xffffffffu, inc, o);
        if (lane >= o) inc += t;
    }
    if (lane == 31) warpTot[wid] = inc;
    __syncthreads();
    if (wid == 0) {
        int wv = (lane < 8) ? warpTot[lane] : 0;
        int winc = wv;
#pragma unroll
        for (int o = 1; o < 8; o <<= 1) {
            int t = __shfl_up_sync(0xffffffffu, winc, o);
            if (lane >= o) winc += t;
        }
        if (lane < 8) warpTot[lane] = winc - wv;   // exclusive warp offsets
        int blockTotal = __shfl_sync(0xffffffffu, winc, 7);
        if (lane == 0) {
            if (blockIdx.x == 0) {
                __threadfence();
                state[0] = ((unsigned long long)blockTotal << 2) | 2ull;  // prefix
                blockOffSh = 0;
                rowptr[n] = e;
            } else {
                __threadfence();
                state[blockIdx.x] = ((unsigned long long)blockTotal << 2) | 1ull;  // aggregate
                int excl = 0;
                int j = blockIdx.x - 1;
                while (true) {
                    unsigned long long vv;
                    do { vv = state[j]; } while ((vv & 3ull) == 0ull);
                    excl += (int)(vv >> 2);
                    if ((vv & 3ull) == 2ull) break;
                    j--;
                }
                __threadfence();
                state[blockIdx.x] = ((unsigned long long)(excl + blockTotal) << 2) | 2ull;
                blockOffSh = excl;
            }
        }
    }
    __syncthreads();
    int run = blockOffSh + warpTot[wid] + (inc - s);
#pragma unroll
    for (int i = 0; i < 8; i++) {
        int idx = tbase + i;
        if (idx < n) {
            rowptr[idx] = run;
            fill[idx] = run;
            run += v[i];
        }
    }
}

__global__ void k_place(const int* __restrict__ src, const int* __restrict__ dst,
                        const float* __restrict__ w, const float* __restrict__ dinv,
                        int* fill, int2* csr, int e) {
    int i = blockIdx.x * blockDim.x + threadIdx.x;
    if (i < e) {
        int s = src[i], d = dst[i];
        float nm = dinv[s] * w[i] * dinv[d];
        int pos = atomicAdd(fill + d, 1);
        csr[pos] = make_int2(s, __float_as_int(nm));
    }
}

// ---------------- tf32 helpers ------------------------------------------------
__device__ __forceinline__ uint32_t f2tf32(float f) {
    uint32_t r;
    asm("cvt.rna.tf32.f32 %0, %1;" : "=r"(r) : "f"(f));
    return r;
}

__device__ __forceinline__ void mma_tf32(float c[4], uint32_t a0, uint32_t a1,
                                         uint32_t a2, uint32_t a3,
                                         uint32_t b0, uint32_t b1) {
    asm volatile(
        "mma.sync.aligned.m16n8k8.row.col.f32.tf32.tf32.f32 "
        "{%0,%1,%2,%3}, {%4,%5,%6,%7}, {%8,%9}, {%0,%1,%2,%3};"
        : "+f"(c[0]), "+f"(c[1]), "+f"(c[2]), "+f"(c[3])
        : "r"(a0), "r"(a1), "r"(a2), "r"(a3), "r"(b0), "r"(b1));
}

// ---------------- tf32 tensor-core GEMM with inline BN(+ReLU) on A ------------
// PDL: B staging (weights, independent) runs pre-wait; stats/A post-wait;
// launch_dependents after A is fully staged (all reads of A done).
template <int K, int NOUT, bool BN>
__global__ void k_gemm_tc(const float* __restrict__ A, const float* __restrict__ B,
                          float* __restrict__ C, int M,
                          const float* __restrict__ gamma, const float* __restrict__ beta,
                          const float* __restrict__ stats, float invN) {
    constexpr int BM = 128;
    constexpr int SA = K + 4;
    constexpr int SB = NOUT + 8;
    constexpr int NT = NOUT / 8;

    extern __shared__ uint32_t sm[];
    uint32_t* As = sm;              // [BM][SA]
    uint32_t* Bs = sm + BM * SA;    // [K][SB]
    __shared__ float sscale[K > 0 ? K : 1];
    __shared__ float sshift[K > 0 ? K : 1];

    const int tid = threadIdx.x;
    const int lane = tid & 31;
    const int warp = tid >> 5;
    const int rowBase = blockIdx.x * BM;

    // --- pre-wait prologue: stage B (weights are harness inputs) ---
    for (int l = tid; l < K * NOUT / 4; l += 256) {
        int r = l / (NOUT / 4);
        int c4 = l % (NOUT / 4);
        float4 v = *reinterpret_cast<const float4*>(B + (size_t)r * NOUT + c4 * 4);
        uint32_t* p = Bs + r * SB + c4 * 4;
        p[0] = f2tf32(v.x); p[1] = f2tf32(v.y); p[2] = f2tf32(v.z); p[3] = f2tf32(v.w);
    }

    pdl_wait();   // predecessor (agg) output now visible

    if (BN && tid < K) {
        float s = stats[tid];
        float q = stats[K + tid];
        float mean = s * invN;
        float var = q * invN - mean * mean;
        float sc = gamma[tid] * rsqrtf(var + EPS);
        sscale[tid] = sc;
        sshift[tid] = beta[tid] - mean * sc;
    }
    if (BN) __syncthreads();   // sscale/sshift visible before A staging

    for (int l = tid; l < BM * K / 4; l += 256) {
        int r = l / (K / 4);
        int c4 = l % (K / 4);
        int gr = rowBase + r;
        float4 v = make_float4(0.f, 0.f, 0.f, 0.f);
        if (gr < M) v = *reinterpret_cast<const float4*>(A + (size_t)gr * K + c4 * 4);
        if (BN) {
            v.x = fmaxf(fmaf(v.x, sscale[c4 * 4 + 0], sshift[c4 * 4 + 0]), 0.f);
            v.y = fmaxf(fmaf(v.y, sscale[c4 * 4 + 1], sshift[c4 * 4 + 1]), 0.f);
            v.z = fmaxf(fmaf(v.z, sscale[c4 * 4 + 2], sshift[c4 * 4 + 2]), 0.f);
            v.w = fmaxf(fmaf(v.w, sscale[c4 * 4 + 3], sshift[c4 * 4 + 3]), 0.f);
        }
        uint32_t* p = As + r * SA + c4 * 4;
        p[0] = f2tf32(v.x); p[1] = f2tf32(v.y); p[2] = f2tf32(v.z); p[3] = f2tf32(v.w);
    }
    __syncthreads();
    pdl_trigger();   // all global reads of A done; dependents may launch

    float acc[NT][4];
#pragma unroll
    for (int nt = 0; nt < NT; nt++) {
        acc[nt][0] = 0.f; acc[nt][1] = 0.f; acc[nt][2] = 0.f; acc[nt][3] = 0.f;
    }

    const int r0 = (warp << 4) + (lane >> 2);
    const int c0 = lane & 3;
    const int bcol = lane >> 2;

#pragma unroll 4
    for (int kk = 0; kk < K; kk += 8) {
        uint32_t a0 = As[r0 * SA + kk + c0];
        uint32_t a1 = As[(r0 + 8) * SA + kk + c0];
        uint32_t a2 = As[r0 * SA + kk + c0 + 4];
        uint32_t a3 = As[(r0 + 8) * SA + kk + c0 + 4];
#pragma unroll
        for (int nt = 0; nt < NT; nt++) {
            uint32_t b0 = Bs[(kk + c0) * SB + nt * 8 + bcol];
            uint32_t b1 = Bs[(kk + c0 + 4) * SB + nt * 8 + bcol];
            mma_tf32(acc[nt], a0, a1, a2, a3, b0, b1);
        }
    }

    int gr0 = rowBase + r0;
    int gr1 = gr0 + 8;
    if (gr0 < M) {
#pragma unroll
        for (int nt = 0; nt < NT; nt++)
            *reinterpret_cast<float2*>(C + (size_t)gr0 * NOUT + nt * 8 + c0 * 2) =
                make_float2(acc[nt][0], acc[nt][1]);
    }
    if (gr1 < M) {
#pragma unroll
        for (int nt = 0; nt < NT; nt++)
            *reinterpret_cast<float2*>(C + (size_t)gr1 * NOUT + nt * 8 + c0 * 2) =
                make_float2(acc[nt][2], acc[nt][3]);
    }
}

// ---------------- pull aggregation (8-edge unroll, 4 accumulator sets) --------
// PDL: trigger immediately (dependent gemm's pre-wait work touches only weights),
// then wait for predecessor gemm's h2.
template <int FEAT, bool STATS>
__global__ void k_agg(const int* __restrict__ rowptr, const int2* __restrict__ csr,
                      const float* __restrict__ h2, const float* __restrict__ bias,
                      const float* __restrict__ normself, float* __restrict__ out,
                      float* stats, int n) {
    constexpr int LPN = FEAT / 4;     // lanes per node
    constexpr int NPW = 32 / LPN;     // nodes per warp
    const int lane = threadIdx.x & 31;
    const int warpG = (blockIdx.x * blockDim.x + threadIdx.x) >> 5;
    const int nWarps = (gridDim.x * blockDim.x) >> 5;
    const int sub = lane / LPN;
    const int fc = lane % LPN;

    pdl_trigger();
    pdl_wait();

    float4 bb = *reinterpret_cast<const float4*>(bias + fc * 4);

    float s0 = 0.f, s1 = 0.f, s2 = 0.f, s3 = 0.f;
    float q0 = 0.f, q1 = 0.f, q2 = 0.f, q3 = 0.f;

    for (int node = warpG * NPW + sub; node < n; node += nWarps * NPW) {
        int beg = rowptr[node];
        int end = rowptr[node + 1];
        float ns = normself[node];
        float4 h = *reinterpret_cast<const float4*>(h2 + (size_t)node * FEAT + fc * 4);
        float4 aA = make_float4(fmaf(ns, h.x, bb.x), fmaf(ns, h.y, bb.y),
                                fmaf(ns, h.z, bb.z), fmaf(ns, h.w, bb.w));
        float4 aB = make_float4(0.f, 0.f, 0.f, 0.f);
        float4 aC = make_float4(0.f, 0.f, 0.f, 0.f);
        float4 aD = make_float4(0.f, 0.f, 0.f, 0.f);
        int e = beg;
        for (; e + 7 < end; e += 8) {
            int2 m0 = csr[e],     m1 = csr[e + 1], m2 = csr[e + 2], m3 = csr[e + 3];
            int2 m4 = csr[e + 4], m5 = csr[e + 5], m6 = csr[e + 6], m7 = csr[e + 7];
            float4 v0 = *reinterpret_cast<const float4*>(h2 + (size_t)m0.x * FEAT + fc * 4);
            float4 v1 = *reinterpret_cast<const float4*>(h2 + (size_t)m1.x * FEAT + fc * 4);
            float4 v2 = *reinterpret_cast<const float4*>(h2 + (size_t)m2.x * FEAT + fc * 4);
            float4 v3 = *reinterpret_cast<const float4*>(h2 + (size_t)m3.x * FEAT + fc * 4);
            float4 v4 = *reinterpret_cast<const float4*>(h2 + (size_t)m4.x * FEAT + fc * 4);
            float4 v5 = *reinterpret_cast<const float4*>(h2 + (size_t)m5.x * FEAT + fc * 4);
            float4 v6 = *reinterpret_cast<const float4*>(h2 + (size_t)m6.x * FEAT + fc * 4);
            float4 v7 = *reinterpret_cast<const float4*>(h2 + (size_t)m7.x * FEAT + fc * 4);
            float n0 = __int_as_float(m0.y), n1 = __int_as_float(m1.y);
            float n2 = __int_as_float(m2.y), n3 = __int_as_float(m3.y);
            float n4 = __int_as_float(m4.y), n5 = __int_as_float(m5.y);
            float n6 = __int_as_float(m6.y), n7 = __int_as_float(m7.y);
            aA.x = fmaf(n0, v0.x, aA.x); aB.x = fmaf(n1, v1.x, aB.x);
            aC.x = fmaf(n2, v2.x, aC.x); aD.x = fmaf(n3, v3.x, aD.x);
            aA.y = fmaf(n0, v0.y, aA.y); aB.y = fmaf(n1, v1.y, aB.y);
            aC.y = fmaf(n2, v2.y, aC.y); aD.y = fmaf(n3, v3.y, aD.y);
            aA.z = fmaf(n0, v0.z, aA.z); aB.z = fmaf(n1, v1.z, aB.z);
            aC.z = fmaf(n2, v2.z, aC.z); aD.z = fmaf(n3, v3.z, aD.z);
            aA.w = fmaf(n0, v0.w, aA.w); aB.w = fmaf(n1, v1.w, aB.w);
            aC.w = fmaf(n2, v2.w, aC.w); aD.w = fmaf(n3, v3.w, aD.w);
            aA.x = fmaf(n4, v4.x, aA.x); aB.x = fmaf(n5, v5.x, aB.x);
            aC.x = fmaf(n6, v6.x, aC.x); aD.x = fmaf(n7, v7.x, aD.x);
            aA.y = fmaf(n4, v4.y, aA.y); aB.y = fmaf(n5, v5.y, aB.y);
            aC.y = fmaf(n6, v6.y, aC.y); aD.y = fmaf(n7, v7.y, aD.y);
            aA.z = fmaf(n4, v4.z, aA.z); aB.z = fmaf(n5, v5.z, aB.z);
            aC.z = fmaf(n6, v6.z, aC.z); aD.z = fmaf(n7, v7.z, aD.z);
            aA.w = fmaf(n4, v4.w, aA.w); aB.w = fmaf(n5, v5.w, aB.w);
            aC.w = fmaf(n6, v6.w, aC.w); aD.w = fmaf(n7, v7.w, aD.w);
        }
        for (; e + 1 < end; e += 2) {
            int2 m0 = csr[e], m1 = csr[e + 1];
            float4 v0 = *reinterpret_cast<const float4*>(h2 + (size_t)m0.x * FEAT + fc * 4);
            float4 v1 = *reinterpret_cast<const float4*>(h2 + (size_t)m1.x * FEAT + fc * 4);
            float n0 = __int_as_float(m0.y), n1 = __int_as_float(m1.y);
            aA.x = fmaf(n0, v0.x, aA.x); aB.x = fmaf(n1, v1.x, aB.x);
            aA.y = fmaf(n0, v0.y, aA.y); aB.y = fmaf(n1, v1.y, aB.y);
            aA.z = fmaf(n0, v0.z, aA.z); aB.z = fmaf(n1, v1.z, aB.z);
            aA.w = fmaf(n0, v0.w, aA.w); aB.w = fmaf(n1, v1.w, aB.w);
        }
        if (e < end) {
            int2 m0 = csr[e];
            float4 v0 = *reinterpret_cast<const float4*>(h2 + (size_t)m0.x * FEAT + fc * 4);
            float n0 = __int_as_float(m0.y);
            aA.x = fmaf(n0, v0.x, aA.x);
            aA.y = fmaf(n0, v0.y, aA.y);
            aA.z = fmaf(n0, v0.z, aA.z);
            aA.w = fmaf(n0, v0.w, aA.w);
        }
        float4 acc = make_float4((aA.x + aB.x) + (aC.x + aD.x),
                                 (aA.y + aB.y) + (aC.y + aD.y),
                                 (aA.z + aB.z) + (aC.z + aD.z),
                                 (aA.w + aB.w) + (aC.w + aD.w));
        *reinterpret_cast<float4*>(out + (size_t)node * FEAT + fc * 4) = acc;
        if (STATS) {
            s0 += acc.x; s1 += acc.y; s2 += acc.z; s3 += acc.w;
            q0 = fmaf(acc.x, acc.x, q0); q1 = fmaf(acc.y, acc.y, q1);
            q2 = fmaf(acc.z, acc.z, q2); q3 = fmaf(acc.w, acc.w, q3);
        }
    }

    if (STATS) {
#pragma unroll
        for (int off = 16; off >= LPN; off >>= 1) {
            s0 += __shfl_down_sync(0xffffffffu, s0, off);
            s1 += __shfl_down_sync(0xffffffffu, s1, off);
            s2 += __shfl_down_sync(0xffffffffu, s2, off);
            s3 += __shfl_down_sync(0xffffffffu, s3, off);
            q0 += __shfl_down_sync(0xffffffffu, q0, off);
            q1 += __shfl_down_sync(0xffffffffu, q1, off);
            q2 += __shfl_down_sync(0xffffffffu, q2, off);
            q3 += __shfl_down_sync(0xffffffffu, q3, off);
        }
        __shared__ float sh_s[8][FEAT];
        __shared__ float sh_q[8][FEAT];
        const int wid = threadIdx.x >> 5;
        if (lane < LPN) {
            sh_s[wid][fc * 4 + 0] = s0; sh_s[wid][fc * 4 + 1] = s1;
            sh_s[wid][fc * 4 + 2] = s2; sh_s[wid][fc * 4 + 3] = s3;
            sh_q[wid][fc * 4 + 0] = q0; sh_q[wid][fc * 4 + 1] = q1;
            sh_q[wid][fc * 4 + 2] = q2; sh_q[wid][fc * 4 + 3] = q3;
        }
        __syncthreads();
        int tid = threadIdx.x;
        if (tid < FEAT) {
            float a = 0.f, b = 0.f;
#pragma unroll
            for (int w = 0; w < 8; w++) { a += sh_s[w][tid]; b += sh_q[w][tid]; }
            atomicAdd(&stats[tid], a);
            atomicAdd(&stats[FEAT + tid], b);
        }
    }
}

// ---------------- host orchestration -----------------------------------------
static inline int cdiv(int a, int b) { return (a + b - 1) / b; }

extern "C" void kernel_launch(void* const* d_in, const int* in_sizes, int n_in,
                              void* d_out, int out_size) {
    const float* x      = (const float*)d_in[0];
    const int*   src    = (const int*)d_in[1];
    const int*   dst    = (const int*)d_in[2];
    const float* weight = (const float*)d_in[3];
    const float* W1 = (const float*)d_in[4];
    const float* b1 = (const float*)d_in[5];
    const float* ga1 = (const float*)d_in[6];
    const float* be1 = (const float*)d_in[7];
    const float* W2 = (const float*)d_in[8];
    const float* b2 = (const float*)d_in[9];
    const float* ga2 = (const float*)d_in[10];
    const float* be2 = (const float*)d_in[11];
    const float* W3 = (const float*)d_in[12];
    const float* b3 = (const float*)d_in[13];

    const int N = in_sizes[0] / 128;
    const int E = in_sizes[1];
    float* outp = (float*)d_out;

    void *p_deg, *p_cnt, *p_fill, *p_rowptr, *p_csr, *p_dinv, *p_ns, *p_h2, *p_out;
    void *p_state, *p_stats;
    cudaGetSymbolAddress(&p_deg, g_deg);
    cudaGetSymbolAddress(&p_cnt, g_cnt);
    cudaGetSymbolAddress(&p_fill, g_fill);
    cudaGetSymbolAddress(&p_rowptr, g_rowptr);
    cudaGetSymbolAddress(&p_csr, g_csr);
    cudaGetSymbolAddress(&p_dinv, g_dinv);
    cudaGetSymbolAddress(&p_ns, g_normself);
    cudaGetSymbolAddress(&p_h2, g_h2);
    cudaGetSymbolAddress(&p_out, g_out);
    cudaGetSymbolAddress(&p_state, g_scanstate);
    cudaGetSymbolAddress(&p_stats, g_stats);
    float* deg = (float*)p_deg;
    int* cnt = (int*)p_cnt;
    int* fill = (int*)p_fill;
    int* rowptr = (int*)p_rowptr;
    int2* csr = (int2*)p_csr;
    float* dinv = (float*)p_dinv;
    float* normself = (float*)p_ns;
    float* h2 = (float*)p_h2;
    float* agg = (float*)p_out;
    unsigned long long* scanstate = (unsigned long long*)p_state;
    float* stats1 = (float*)p_stats;        // layer1: 256 floats
    float* stats2 = (float*)p_stats + 256;  // layer2: 128 floats

    const float invN = 1.0f / (float)N;

    const int smem1 = (128 * (128 + 4) + 128 * (128 + 8)) * 4;
    const int smem2 = (128 * (128 + 4) + 128 * (64 + 8)) * 4;
    const int smem3 = (128 * (64 + 4) + 64 * (32 + 8)) * 4;
    cudaFuncSetAttribute(k_gemm_tc<128, 128, false>,
                         cudaFuncAttributeMaxDynamicSharedMemorySize, smem1);
    cudaFuncSetAttribute(k_gemm_tc<128, 64, true>,
                         cudaFuncAttributeMaxDynamicSharedMemorySize, smem2);
    cudaFuncSetAttribute(k_gemm_tc<64, 32, true>,
                         cudaFuncAttributeMaxDynamicSharedMemorySize, smem3);

    // side stream + fork/join events (host-side objects only)
    cudaStream_t s2;
    cudaEvent_t evFork, evJoin;
    cudaStreamCreateWithFlags(&s2, cudaStreamNonBlocking);
    cudaEventCreateWithFlags(&evFork, cudaEventDisableTiming);
    cudaEventCreateWithFlags(&evJoin, cudaEventDisableTiming);

    const int scanGrid = cdiv(N, 2048);   // 25 blocks for N=50000
    const int gemmGrid = cdiv(N, 128);
    const int aggGrid = 1184;             // 8 blocks/SM

    // ---- fork: CSR/normalization prep on s2, concurrent with Layer-1 GEMM ----
    cudaEventRecord(evFork, 0);
    cudaStreamWaitEvent(s2, evFork, 0);

    k_init<<<cdiv(N, 256), 256, 0, s2>>>(deg, cnt, stats1, scanstate, N);
    k_prep_edge<<<cdiv(E, 256), 256, 0, s2>>>(dst, weight, deg, cnt, E);
    k_scan<<<scanGrid, 256, 0, s2>>>(cnt, deg, dinv, normself, rowptr, fill, scanstate, N, E);
    k_place<<<cdiv(E, 256), 256, 0, s2>>>(src, dst, weight, dinv, fill, csr, E);
    cudaEventRecord(evJoin, s2);

    // Layer-1 GEMM on main stream (independent of prep)
    k_gemm_tc<128, 128, false><<<gemmGrid, 256, smem1>>>(x, W1, h2, N,
                                                         nullptr, nullptr, nullptr, invN);

    // ---- join: everything after needs both GEMM1 and the CSR ----
    cudaStreamWaitEvent(0, evJoin, 0);

    // agg1: plain launch (predecessor is an event-wait, not a kernel)
    k_agg<128, true><<<aggGrid, 256>>>(rowptr, csr, h2, b1, normself, agg, stats1, N);

    // PDL launch config for the rest of the chain
    cudaLaunchAttribute pdlAttr[1];
    pdlAttr[0].id = cudaLaunchAttributeProgrammaticStreamSerialization;
    pdlAttr[0].val.programmaticStreamSerializationAllowed = 1;

    {
        cudaLaunchConfig_t cfg{};
        cfg.gridDim = dim3(gemmGrid, 1, 1);
        cfg.blockDim = dim3(256, 1, 1);
        cfg.dynamicSmemBytes = smem2;
        cfg.stream = 0;
        cfg.attrs = pdlAttr;
        cfg.numAttrs = 1;
        cudaLaunchKernelEx(&cfg, k_gemm_tc<128, 64, true>, agg, W2, h2, N,
                           ga1, be1, (const float*)stats1, invN);
    }
    {
        cudaLaunchConfig_t cfg{};
        cfg.gridDim = dim3(aggGrid, 1, 1);
        cfg.blockDim = dim3(256, 1, 1);
        cfg.dynamicSmemBytes = 0;
        cfg.stream = 0;
        cfg.attrs = pdlAttr;
        cfg.numAttrs = 1;
        cudaLaunchKernelEx(&cfg, k_agg<64, true>, (const int*)rowptr, (const int2*)csr,
                           (const float*)h2, b2, (const float*)normself, agg, stats2, N);
    }
    {
        cudaLaunchConfig_t cfg{};
        cfg.gridDim = dim3(gemmGrid, 1, 1);
        cfg.blockDim = dim3(256, 1, 1);
        cfg.dynamicSmemBytes = smem3;
        cfg.stream = 0;
        cfg.attrs = pdlAttr;
        cfg.numAttrs = 1;
        cudaLaunchKernelEx(&cfg, k_gemm_tc<64, 32, true>, (const float*)agg, W3, h2, N,
                           ga2, be2, (const float*)stats2, invN);
    }
    {
        cudaLaunchConfig_t cfg{};
        cfg.gridDim = dim3(aggGrid, 1, 1);
        cfg.blockDim = dim3(256, 1, 1);
        cfg.dynamicSmemBytes = 0;
        cfg.stream = 0;
        cfg.attrs = pdlAttr;
        cfg.numAttrs = 1;
        cudaLaunchKernelEx(&cfg, k_agg<32, false>, (const int*)rowptr, (const int2*)csr,
                           (const float*)h2, b3, (const float*)normself, outp,
                           (float*)nullptr, N);
    }
}